// round 14
// baseline (speedup 1.0000x reference)
#include <cuda_runtime.h>
#include <cuda_bf16.h>
#include <cstdint>
#include <math.h>

#define HH      256
#define G4      1024
#define BATCH   256
#define WIN     512
#define TT      519     // W + MAXLAG
#define MAXLAG  7
#define SREP    100
#define NDEC    25600   // BATCH * SREP
#define PSTEPS  24
#define ESTEPS  512
#define ENC_BLOCKS 128

// ---- encoder v4 smem layout (4-byte units) ----
#define WPK    132
#define MATSZ  (2 * 64 * WPK)
#define OFF_CHH (3 * MATSZ)
#define OFF_CHL (OFF_CHH + 1536)
#define OFF_RED (OFF_CHL + 1536)
#define OFF_SXW (OFF_RED + 32 * 68)
#define OFF_SXA (OFF_SXW + 64 * 8)
#define ENC_SMEM_UNITS (OFF_SXA + 32 * 8)
#define ENC_SMEM_BYTES (ENC_SMEM_UNITS * 4)

// ---- decoder dynamic smem (bytes): 2-buffer mma tiles + bias ----
#define DBM 128
#define DPK 12
#define DTILEU (DBM * DPK)
#define DO_AH  0
#define DO_AL  (2 * DTILEU * 4)
#define DO_BH  (4 * DTILEU * 4)
#define DO_BL  (6 * DTILEU * 4)
#define DO_BIAS (8 * DTILEU * 4)
#define DEC_SMEM_BYTES (DO_BIAS + 512)

#define WLO    (G4 * 128)     // lo offset within a split weight matrix
#define WLAGLO (G4 * 8)

// ---------------- scratch ----------------
__device__ __align__(128) float g_scaled[BATCH * TT];
__device__ float g_loc[BATCH];
__device__ float g_scale[BATCH];

__device__ __align__(128) float g_h0e[2][BATCH * HH];
__device__ __align__(128) float g_c0e[BATCH * HH];
__device__ __align__(128) float g_h1e[2][BATCH * HH];
__device__ __align__(128) float g_c1e[BATCH * HH];

__device__ __align__(128) float g_h0d[2][NDEC * HH];
__device__ __align__(128) float g_c0d[NDEC * HH];
__device__ __align__(128) float g_h1d[2][NDEC * HH];
__device__ __align__(128) float g_c1d[NDEC * HH];

__device__ __align__(128) float g_hist[NDEC * 32];
__device__ __align__(128) float g_musig[PSTEPS * NDEC * 2];

// pre-split decoder weights: [mat] x (hi[G4*128], lo[G4*128]); lag separate
__device__ __align__(128) unsigned g_wsp[3 * 2 * G4 * 128];
__device__ __align__(128) unsigned g_wlag[2 * G4 * 8];

__device__ unsigned g_ectr = 0;

__device__ __forceinline__ float sigf(float x) { return 1.0f / (1.0f + expf(-x)); }

#define MMA_BF16(c, a, b) \
    asm volatile("mma.sync.aligned.m16n8k16.row.col.f32.bf16.bf16.f32 " \
                 "{%0,%1,%2,%3}, {%4,%5,%6,%7}, {%8,%9}, {%0,%1,%2,%3};\n" \
                 : "+f"((c)[0]), "+f"((c)[1]), "+f"((c)[2]), "+f"((c)[3]) \
                 : "r"((a)[0]), "r"((a)[1]), "r"((a)[2]), "r"((a)[3]), \
                   "r"((b)[0]), "r"((b)[1]))

__device__ __forceinline__ void bsplit2(float x, float y, unsigned& hi, unsigned& lo) {
    __nv_bfloat16 hx = __float2bfloat16(x);
    __nv_bfloat16 hy = __float2bfloat16(y);
    __nv_bfloat162 hp = __halves2bfloat162(hx, hy);
    __nv_bfloat162 lp = __halves2bfloat162(
        __float2bfloat16(x - __bfloat162float(hx)),
        __float2bfloat16(y - __bfloat162float(hy)));
    hi = *reinterpret_cast<unsigned*>(&hp);
    lo = *reinterpret_cast<unsigned*>(&lp);
}

// ---------------- normalization ----------------
__global__ void norm_kernel(const float* __restrict__ tp) {
    int b = blockIdx.x;
    int tid = threadIdx.x;
    const float* row = tp + b * TT;

    double s = 0.0, q = 0.0;
    for (int j = tid; j < WIN; j += blockDim.x) {
        double v = (double)row[MAXLAG + j];
        s += v; q += v * v;
    }
    __shared__ double ss[256], sq[256];
    ss[tid] = s; sq[tid] = q;
    __syncthreads();
    for (int o = 128; o > 0; o >>= 1) {
        if (tid < o) { ss[tid] += ss[tid + o]; sq[tid] += sq[tid + o]; }
        __syncthreads();
    }
    __shared__ float smean, sscale;
    if (tid == 0) {
        double mean = ss[0] / (double)WIN;
        double var  = sq[0] / (double)WIN - mean * mean;
        if (var < 0.0) var = 0.0;
        float sd = (float)sqrt(var);
        float sc = (sd < 1e-10f) ? 1.0f : sd;
        smean = (float)mean; sscale = sc;
        g_loc[b] = (float)mean; g_scale[b] = sc;
    }
    __syncthreads();
    float m = smean, sc = sscale;
    for (int j = tid; j < TT; j += blockDim.x)
        g_scaled[b * TT + j] = (row[j] - m) / sc;
}

__global__ void zero_enc_kernel() {
    int i = blockIdx.x * blockDim.x + threadIdx.x;
    if (i < BATCH * HH) {
        g_h0e[0][i] = 0.f; g_c0e[i] = 0.f;
        g_h1e[0][i] = 0.f; g_c1e[i] = 0.f;
    }
    if (i == 0) g_ectr = 0;
}

// ---------------- weight pre-split for decoder ----------------
__global__ void split_weights(const float* __restrict__ w_hh0,
                              const float* __restrict__ w_ih1,
                              const float* __restrict__ w_hh1,
                              const float* __restrict__ w_ih0) {
    int row = blockIdx.x;          // gate row 0..1023
    int kp  = threadIdx.x;         // 0..127
    unsigned hi, lo;
    bsplit2(w_hh0[row * 256 + 2 * kp], w_hh0[row * 256 + 2 * kp + 1], hi, lo);
    g_wsp[0 * 2 * WLO + row * 128 + kp] = hi;
    g_wsp[0 * 2 * WLO + WLO + row * 128 + kp] = lo;
    bsplit2(w_ih1[row * 256 + 2 * kp], w_ih1[row * 256 + 2 * kp + 1], hi, lo);
    g_wsp[1 * 2 * WLO + row * 128 + kp] = hi;
    g_wsp[1 * 2 * WLO + WLO + row * 128 + kp] = lo;
    bsplit2(w_hh1[row * 256 + 2 * kp], w_hh1[row * 256 + 2 * kp + 1], hi, lo);
    g_wsp[2 * 2 * WLO + row * 128 + kp] = hi;
    g_wsp[2 * 2 * WLO + WLO + row * 128 + kp] = lo;
    if (kp < 8) {
        float x = (2 * kp < 7)     ? w_ih0[row * 7 + 2 * kp]     : 0.f;
        float y = (2 * kp + 1 < 7) ? w_ih0[row * 7 + 2 * kp + 1] : 0.f;
        bsplit2(x, y, hi, lo);
        g_wlag[row * 8 + kp] = hi;
        g_wlag[WLAGLO + row * 8 + kp] = lo;
    }
}

// ---------------- persistent encoder v4 (unchanged from R9/R13 wins) ----------------
__global__ void __launch_bounds__(512) encoder_kernel(
    const float* __restrict__ w_ih0, const float* __restrict__ w_hh0,
    const float* __restrict__ b_ih0, const float* __restrict__ b_hh0,
    const float* __restrict__ w_ih1, const float* __restrict__ w_hh1,
    const float* __restrict__ b_ih1, const float* __restrict__ b_hh1)
{
    extern __shared__ unsigned esu[];
    float* esf = reinterpret_cast<float*>(esu);
    unsigned* W0h  = esu;                 unsigned* W0l  = esu + 64 * WPK;
    unsigned* WI1h = esu + MATSZ;         unsigned* WI1l = esu + MATSZ + 64 * WPK;
    unsigned* WH1h = esu + 2 * MATSZ;     unsigned* WH1l = esu + 2 * MATSZ + 64 * WPK;
    unsigned* CHH  = esu + OFF_CHH;
    unsigned* CHL  = esu + OFF_CHL;
    float* RED = esf + OFF_RED;
    float* SXW = esf + OFF_SXW;
    float* SXA = esf + OFF_SXA;

    const int t    = threadIdx.x;
    const int lane = t & 31;
    const int w    = t >> 5;
    const int grp  = w >> 3;
    const int wl   = w & 7;
    const int m_w  = (wl & 1) * 16;
    const int n_w  = (wl >> 1) * 16;
    const int qr   = lane >> 2;
    const int qc   = lane & 3;
    const int b0   = (blockIdx.x & 7) * 32;
    const int u0   = (blockIdx.x >> 3) * 16;

    for (int i = t; i < 64 * 128; i += 512) {
        int r  = i >> 7;
        int kp = i & 127;
        int grow = u0 + (r & 15) + ((r >> 4) << 8);
        unsigned hi, lo;
        bsplit2(w_hh0[grow * 256 + 2 * kp], w_hh0[grow * 256 + 2 * kp + 1], hi, lo);
        W0h[r * WPK + kp] = hi;  W0l[r * WPK + kp] = lo;
        bsplit2(w_ih1[grow * 256 + 2 * kp], w_ih1[grow * 256 + 2 * kp + 1], hi, lo);
        WI1h[r * WPK + kp] = hi; WI1l[r * WPK + kp] = lo;
        bsplit2(w_hh1[grow * 256 + 2 * kp], w_hh1[grow * 256 + 2 * kp + 1], hi, lo);
        WH1h[r * WPK + kp] = hi; WH1l[r * WPK + kp] = lo;
    }
    if (t < 64) {
        int grow = u0 + (t & 15) + ((t >> 4) << 8);
#pragma unroll
        for (int k = 0; k < 7; k++) SXW[t * 8 + k] = w_ih0[grow * 7 + k];
    }

    const int eul = t & 15;
    const int er  = t >> 4;
    float bI0 = 0, bF0 = 0, bG0 = 0, bO0 = 0, bI1 = 0, bF1 = 0, bG1 = 0, bO1 = 0;
    if (t < 256) {
        int u = u0 + eul;
        bI0 = b_ih0[u]       + b_hh0[u];
        bF0 = b_ih0[u + 256] + b_hh0[u + 256];
        bG0 = b_ih0[u + 512] + b_hh0[u + 512];
        bO0 = b_ih0[u + 768] + b_hh0[u + 768];
        bI1 = b_ih1[u]       + b_hh1[u];
        bF1 = b_ih1[u + 256] + b_hh1[u + 256];
        bG1 = b_ih1[u + 512] + b_hh1[u + 512];
        bO1 = b_ih1[u + 768] + b_hh1[u + 768];
    }
    __syncthreads();

    const int gt   = t & 255;
    const int prow = gt >> 3;
    const int pc   = gt & 7;
    unsigned* CHHg = CHH + grp * 768;
    unsigned* CHLg = CHL + grp * 768;

    auto gemm_tc = [&](const float* act, const unsigned* Wh, const unsigned* Wl,
                       float (&acc)[2][4]) {
        const int kb  = grp * 128;
        const int kpb = grp * 64;
        {
            float2 p = __ldcg((const float2*)(act + (b0 + prow) * HH + kb + pc * 2));
            unsigned hi, lo; bsplit2(p.x, p.y, hi, lo);
            CHHg[prow * 12 + pc] = hi;
            CHLg[prow * 12 + pc] = lo;
        }
        __syncthreads();
        for (int ch = 0; ch < 8; ch++) {
            float2 nxt;
            const bool have = (ch + 1) < 8;
            if (have)
                nxt = __ldcg((const float2*)(act + (b0 + prow) * HH + kb + (ch + 1) * 16 + pc * 2));
            const unsigned* hbh = CHHg + (ch & 1) * 384;
            const unsigned* hbl = CHLg + (ch & 1) * 384;
            unsigned ahi[4], alo[4];
            ahi[0] = hbh[(m_w + qr) * 12 + qc];
            ahi[1] = hbh[(m_w + qr + 8) * 12 + qc];
            ahi[2] = hbh[(m_w + qr) * 12 + qc + 4];
            ahi[3] = hbh[(m_w + qr + 8) * 12 + qc + 4];
            alo[0] = hbl[(m_w + qr) * 12 + qc];
            alo[1] = hbl[(m_w + qr + 8) * 12 + qc];
            alo[2] = hbl[(m_w + qr) * 12 + qc + 4];
            alo[3] = hbl[(m_w + qr + 8) * 12 + qc + 4];
#pragma unroll
            for (int f = 0; f < 2; f++) {
                int wr  = (n_w + f * 8 + qr) * WPK + kpb + ch * 8;
                unsigned bhi[2] = {Wh[wr + qc], Wh[wr + qc + 4]};
                unsigned blo[2] = {Wl[wr + qc], Wl[wr + qc + 4]};
                MMA_BF16(acc[f], ahi, bhi);
                MMA_BF16(acc[f], ahi, blo);
                MMA_BF16(acc[f], alo, bhi);
            }
            if (have) {
                unsigned hi, lo; bsplit2(nxt.x, nxt.y, hi, lo);
                CHHg[((ch + 1) & 1) * 384 + prow * 12 + pc] = hi;
                CHLg[((ch + 1) & 1) * 384 + prow * 12 + pc] = lo;
            }
            __syncthreads();
        }
    };

    auto reduce_store = [&](float (&acc)[2][4]) {
        if (grp == 1) {
#pragma unroll
            for (int f = 0; f < 2; f++)
#pragma unroll
                for (int half = 0; half < 2; half++)
#pragma unroll
                    for (int j = 0; j < 2; j++)
                        RED[(m_w + qr + half * 8) * 68 + n_w + f * 8 + 2 * qc + j] =
                            acc[f][half * 2 + j];
        }
        __syncthreads();
        if (grp == 0) {
#pragma unroll
            for (int f = 0; f < 2; f++)
#pragma unroll
                for (int half = 0; half < 2; half++)
#pragma unroll
                    for (int j = 0; j < 2; j++)
                        RED[(m_w + qr + half * 8) * 68 + n_w + f * 8 + 2 * qc + j] +=
                            acc[f][half * 2 + j];
        }
        __syncthreads();
    };

    for (int step = 0; step < ESTEPS; step++) {
        const int pa = step & 1, pb = pa ^ 1;
        float* h0b = g_h0e[pb];
        float* h1b = g_h1e[pb];

        if (t < 32) {
            const float* xr = g_scaled + (b0 + t) * TT + step + 6;
#pragma unroll
            for (int k = 0; k < 7; k++) SXA[t * 8 + k] = xr[-k];
        }

        float acc[2][4];
#pragma unroll
        for (int f = 0; f < 2; f++)
#pragma unroll
            for (int r = 0; r < 4; r++) acc[f][r] = 0.f;

        gemm_tc(g_h0e[pa], W0h, W0l, acc);
        reduce_store(acc);

        if (t < 256) {
#pragma unroll
            for (int h2 = 0; h2 < 2; h2++) {
                int r = er + 16 * h2;
                float gi = RED[r * 68 + eul]      + bI0;
                float gf = RED[r * 68 + 16 + eul] + bF0;
                float gg = RED[r * 68 + 32 + eul] + bG0;
                float go = RED[r * 68 + 48 + eul] + bO0;
#pragma unroll
                for (int k = 0; k < 7; k++) {
                    float x = SXA[r * 8 + k];
                    gi = fmaf(x, SXW[eul * 8 + k], gi);
                    gf = fmaf(x, SXW[(16 + eul) * 8 + k], gf);
                    gg = fmaf(x, SXW[(32 + eul) * 8 + k], gg);
                    go = fmaf(x, SXW[(48 + eul) * 8 + k], go);
                }
                int idx = (b0 + r) * HH + (u0 + eul);
                float c = g_c0e[idx];
                float cn = sigf(gf) * c + sigf(gi) * tanhf(gg);
                g_c0e[idx] = cn;
                h0b[idx] = sigf(go) * tanhf(cn);
            }
        }
        __syncthreads();
        if (t == 0) { __threadfence(); atomicAdd(&g_ectr, 1u); }

#pragma unroll
        for (int f = 0; f < 2; f++)
#pragma unroll
            for (int r = 0; r < 4; r++) acc[f][r] = 0.f;

        if (t == 0) {
            unsigned tgt = 256u * (unsigned)step;
            while (*(volatile unsigned*)&g_ectr < tgt) { }
        }
        __syncthreads();
        gemm_tc(g_h1e[pa], WH1h, WH1l, acc);

        if (t == 0) {
            unsigned tgt = 256u * (unsigned)step + 128u;
            while (*(volatile unsigned*)&g_ectr < tgt) { }
        }
        __syncthreads();
        gemm_tc(h0b, WI1h, WI1l, acc);

        reduce_store(acc);

        if (t < 256) {
#pragma unroll
            for (int h2 = 0; h2 < 2; h2++) {
                int r = er + 16 * h2;
                float gi = RED[r * 68 + eul]      + bI1;
                float gf = RED[r * 68 + 16 + eul] + bF1;
                float gg = RED[r * 68 + 32 + eul] + bG1;
                float go = RED[r * 68 + 48 + eul] + bO1;
                int idx = (b0 + r) * HH + (u0 + eul);
                float c = g_c1e[idx];
                float cn = sigf(gf) * c + sigf(gi) * tanhf(gg);
                g_c1e[idx] = cn;
                h1b[idx] = sigf(go) * tanhf(cn);
            }
        }
        __syncthreads();
        if (t == 0) { __threadfence(); atomicAdd(&g_ectr, 1u); }
    }
}

// ---------------- decoder cell v7: v6 + pre-split B (pure copy staging) ----------------
__global__ void __launch_bounds__(256) dec_cell_bf16(
    const float* __restrict__ xs,            // lag base (g_hist + p + 6) or null
    const unsigned* __restrict__ wlag,       // pre-split lag weights or null
    const float* __restrict__ xb,            // big x (N,256) or null
    const unsigned* __restrict__ wspb,       // pre-split weights for xb segment
    const float* __restrict__ h_in,          // (N,256)
    const unsigned* __restrict__ wsph,       // pre-split weights for h segment
    const float* __restrict__ b_ih, const float* __restrict__ b_hh,
    const float* __restrict__ c_in,
    float* __restrict__ h_out, float* __restrict__ c_out,
    // layer-0 sampling prologue (p>0):
    const float* __restrict__ musig_in, const float* __restrict__ eps_prev,
    const float* __restrict__ b_mu, const float* __restrict__ b_sig, int pm1,
    // layer-1 head partials:
    const float* __restrict__ w_mu, const float* __restrict__ w_sig,
    float* __restrict__ musig_out)
{
    extern __shared__ __align__(128) char dsm[];
    unsigned* tAhi = (unsigned*)(dsm + DO_AH);
    unsigned* tAlo = (unsigned*)(dsm + DO_AL);
    unsigned* tBhi = (unsigned*)(dsm + DO_BH);
    unsigned* tBlo = (unsigned*)(dsm + DO_BL);
    float* sBias = (float*)(dsm + DO_BIAS);

    const int t    = threadIdx.x;
    const int lane = t & 31;
    const int wid  = t >> 5;
    const int m0w  = (wid & 1) * 64;
    const int u0w  = (wid >> 1) * 8;
    const int b0   = blockIdx.x * DBM;
    const int u0   = blockIdx.y * 32;

    const int lrow = t >> 1;
    const int lc0  = (t & 1) * 8;
    const int lp0  = (t & 1) * 4;
    const int lgrow = u0 + (lrow & 31) + ((lrow >> 5) << 8);

    if (t < 128) {
        int grow = u0 + (t & 31) + ((t >> 5) << 8);
        sBias[t] = b_ih[grow] + b_hh[grow];
    }

    // ---- layer-0 prologue: materialize previous step's sample into hist ----
    if (musig_in != nullptr) {
        if (t < DBM) {
            int row = b0 + t;
            float mu = musig_in[row * 2]     + b_mu[0];
            float sg = musig_in[row * 2 + 1] + b_sig[0];
            float sp = (sg > 20.f) ? sg : log1pf(expf(sg));
            g_hist[row * 32 + MAXLAG + pm1] = mu + sp * eps_prev[row];
        }
        __syncthreads();
    }

    float acc[4][4][4];
#pragma unroll
    for (int mi = 0; mi < 4; mi++)
#pragma unroll
        for (int g = 0; g < 4; g++)
#pragma unroll
            for (int r = 0; r < 4; r++) acc[mi][g][r] = 0.f;

    const int qr = lane >> 2;
    const int qc = lane & 3;

    auto compute_chunk = [&](int buf) {
        const unsigned* AH = tAhi + buf * DTILEU;
        const unsigned* AL = tAlo + buf * DTILEU;
        const unsigned* BH = tBhi + buf * DTILEU;
        const unsigned* BL = tBlo + buf * DTILEU;
        unsigned ahi[4][4], alo[4][4];
#pragma unroll
        for (int mi = 0; mi < 4; mi++) {
            int r = m0w + mi * 16 + qr;
            ahi[mi][0] = AH[r * DPK + qc];       ahi[mi][1] = AH[(r + 8) * DPK + qc];
            ahi[mi][2] = AH[r * DPK + qc + 4];   ahi[mi][3] = AH[(r + 8) * DPK + qc + 4];
            alo[mi][0] = AL[r * DPK + qc];       alo[mi][1] = AL[(r + 8) * DPK + qc];
            alo[mi][2] = AL[r * DPK + qc + 4];   alo[mi][3] = AL[(r + 8) * DPK + qc + 4];
        }
        unsigned bhi[4][2], blo[4][2];
#pragma unroll
        for (int g = 0; g < 4; g++) {
            int br = g * 32 + u0w + qr;
            bhi[g][0] = BH[br * DPK + qc]; bhi[g][1] = BH[br * DPK + qc + 4];
            blo[g][0] = BL[br * DPK + qc]; blo[g][1] = BL[br * DPK + qc + 4];
        }
#pragma unroll
        for (int mi = 0; mi < 4; mi++)
#pragma unroll
            for (int g = 0; g < 4; g++) {
                MMA_BF16(acc[mi][g], ahi[mi], bhi[g]);
                MMA_BF16(acc[mi][g], ahi[mi], blo[g]);
                MMA_BF16(acc[mi][g], alo[mi], bhi[g]);
            }
    };

    auto store_a8 = [&](int buf, const float* v) {
        unsigned hi[4], lo[4];
#pragma unroll
        for (int j = 0; j < 4; j++) bsplit2(v[2 * j], v[2 * j + 1], hi[j], lo[j]);
        *(uint4*)(tAhi + buf * DTILEU + lrow * DPK + lp0) = make_uint4(hi[0], hi[1], hi[2], hi[3]);
        *(uint4*)(tAlo + buf * DTILEU + lrow * DPK + lp0) = make_uint4(lo[0], lo[1], lo[2], lo[3]);
    };

    int tb = 0;

    // -------- lag chunk: A runtime-split, B pure copy --------
    if (xs != nullptr) {
        float va[8];
#pragma unroll
        for (int cc = 0; cc < 8; cc++) {
            int k = lc0 + cc;
            va[cc] = (k < 7) ? xs[(b0 + lrow) * 32 - k] : 0.f;
        }
        store_a8(tb, va);
        *(uint4*)(tBhi + tb * DTILEU + lrow * DPK + lp0) =
            *(const uint4*)(wlag + lgrow * 8 + lp0);
        *(uint4*)(tBlo + tb * DTILEU + lrow * DPK + lp0) =
            *(const uint4*)(wlag + WLAGLO + lgrow * 8 + lp0);
        __syncthreads();
        compute_chunk(tb);
        tb ^= 1;
    }

    // -------- dense K=256 segments: one sync per chunk, B pure copy --------
    auto gemm_segment = [&](const float* __restrict__ act, const unsigned* __restrict__ wsp) {
        for (int k0 = 0; k0 < HH; k0 += 16) {
            const int kp = k0 >> 1;
            float av[8];
            *(float4*)(av)     = *(const float4*)(act + (long long)(b0 + lrow) * HH + k0 + lc0);
            *(float4*)(av + 4) = *(const float4*)(act + (long long)(b0 + lrow) * HH + k0 + lc0 + 4);
            uint4 bh = *(const uint4*)(wsp + (long long)lgrow * 128 + kp + lp0);
            uint4 bl = *(const uint4*)(wsp + WLO + (long long)lgrow * 128 + kp + lp0);
            store_a8(tb, av);
            *(uint4*)(tBhi + tb * DTILEU + lrow * DPK + lp0) = bh;
            *(uint4*)(tBlo + tb * DTILEU + lrow * DPK + lp0) = bl;
            __syncthreads();
            compute_chunk(tb);
            tb ^= 1;
        }
    };

    if (xb != nullptr) gemm_segment(xb, wspb);
    gemm_segment(h_in, wsph);

    // -------- epilogue: fused LSTM + optional head partials --------
    float wmu[2] = {0.f, 0.f}, wsg[2] = {0.f, 0.f};
    if (w_mu != nullptr) {
#pragma unroll
        for (int j = 0; j < 2; j++) {
            int u = u0 + u0w + 2 * qc + j;
            wmu[j] = w_mu[u];
            wsg[j] = w_sig[u];
        }
    }
#pragma unroll
    for (int mi = 0; mi < 4; mi++) {
        int rbase = b0 + m0w + mi * 16 + qr;
#pragma unroll
        for (int half = 0; half < 2; half++) {
            int row = rbase + half * 8;
            float hn2[2];
#pragma unroll
            for (int j = 0; j < 2; j++) {
                int ucol = 2 * qc + j;
                int u = u0 + u0w + ucol;
                int ci = half * 2 + j;
                float gi_ = acc[mi][0][ci] + sBias[ 0 + u0w + ucol];
                float gf  = acc[mi][1][ci] + sBias[32 + u0w + ucol];
                float gg  = acc[mi][2][ci] + sBias[64 + u0w + ucol];
                float go  = acc[mi][3][ci] + sBias[96 + u0w + ucol];
                long long idx = (long long)row * HH + u;
                float c = c_in[idx];
                float cn = sigf(gf) * c + sigf(gi_) * tanhf(gg);
                float hn = sigf(go) * tanhf(cn);
                c_out[idx] = cn;
                h_out[idx] = hn;
                hn2[j] = hn;
            }
            if (w_mu != nullptr) {
                float pm = hn2[0] * wmu[0] + hn2[1] * wmu[1];
                float ps = hn2[0] * wsg[0] + hn2[1] * wsg[1];
                pm += __shfl_xor_sync(0xffffffffu, pm, 1);
                ps += __shfl_xor_sync(0xffffffffu, ps, 1);
                pm += __shfl_xor_sync(0xffffffffu, pm, 2);
                ps += __shfl_xor_sync(0xffffffffu, ps, 2);
                if (qc == 0) {
                    atomicAdd(&musig_out[(long long)row * 2],     pm);
                    atomicAdd(&musig_out[(long long)row * 2 + 1], ps);
                }
            }
        }
    }
}

// ---------------- replicate encoder state x100 + init history + zero musig ----------------
__global__ void replicate_kernel() {
    int row = blockIdx.x;
    int u   = threadIdx.x;
    int b   = row / SREP;
    long long d = (long long)row * HH + u;
    long long s = (long long)b * HH + u;
    g_h0d[0][d] = g_h0e[0][s];
    g_c0d[d]    = g_c0e[s];
    g_h1d[0][d] = g_h1e[0][s];
    g_c1d[d]    = g_c1e[s];
    if (u < MAXLAG) g_hist[row * 32 + u] = g_scaled[b * TT + WIN + u];
    if (u < 2 * PSTEPS)
        g_musig[(long long)(u >> 1) * NDEC * 2 + (long long)row * 2 + (u & 1)] = 0.f;
}

// ---------------- mean over samples (from musig) + denormalize ----------------
__global__ void reduce_kernel(float* __restrict__ out,
                              const float* __restrict__ eps,
                              const float* __restrict__ b_mu,
                              const float* __restrict__ b_sig) {
    int gid  = blockIdx.x * blockDim.x + threadIdx.x;
    int warp = gid >> 5;
    int lane = gid & 31;
    if (warp >= BATCH * PSTEPS) return;
    int b = warp / PSTEPS;
    int p = warp % PSTEPS;
    const float bmu = b_mu[0], bsg = b_sig[0];
    float s = 0.f;
    for (int ss = lane; ss < SREP; ss += 32) {
        long long row = (long long)b * SREP + ss;
        const float* ms = g_musig + ((long long)p * NDEC + row) * 2;
        float mu = ms[0] + bmu;
        float sg = ms[1] + bsg;
        float sp = (sg > 20.f) ? sg : log1pf(expf(sg));
        s += mu + sp * eps[(long long)p * NDEC + row];
    }
#pragma unroll
    for (int o = 16; o > 0; o >>= 1) s += __shfl_xor_sync(0xffffffffu, s, o);
    if (lane == 0)
        out[b * PSTEPS + p] = s * (1.0f / (float)SREP) * g_scale[b] + g_loc[b];
}

// ---------------- launch ----------------
extern "C" void kernel_launch(void* const* d_in, const int* in_sizes, int n_in,
                              void* d_out, int out_size) {
    const float* targets = (const float*)d_in[0];
    const float* w_ih0   = (const float*)d_in[1];
    const float* w_hh0   = (const float*)d_in[2];
    const float* b_ih0   = (const float*)d_in[3];
    const float* b_hh0   = (const float*)d_in[4];
    const float* w_ih1   = (const float*)d_in[5];
    const float* w_hh1   = (const float*)d_in[6];
    const float* b_ih1   = (const float*)d_in[7];
    const float* b_hh1   = (const float*)d_in[8];
    const float* w_mu    = (const float*)d_in[9];
    const float* b_mu    = (const float*)d_in[10];
    const float* w_sigma = (const float*)d_in[11];
    const float* b_sigma = (const float*)d_in[12];
    const float* eps     = (const float*)d_in[13];
    float* out = (float*)d_out;

    float *h0d, *c0d, *h1d, *c1d, *hist, *musig;
    unsigned *wsp, *wlag;
    cudaGetSymbolAddress((void**)&h0d, g_h0d);
    cudaGetSymbolAddress((void**)&c0d, g_c0d);
    cudaGetSymbolAddress((void**)&h1d, g_h1d);
    cudaGetSymbolAddress((void**)&c1d, g_c1d);
    cudaGetSymbolAddress((void**)&hist, g_hist);
    cudaGetSymbolAddress((void**)&musig, g_musig);
    cudaGetSymbolAddress((void**)&wsp, g_wsp);
    cudaGetSymbolAddress((void**)&wlag, g_wlag);

    cudaFuncSetAttribute(encoder_kernel,
                         cudaFuncAttributeMaxDynamicSharedMemorySize, ENC_SMEM_BYTES);
    cudaFuncSetAttribute(dec_cell_bf16,
                         cudaFuncAttributeMaxDynamicSharedMemorySize, DEC_SMEM_BYTES);

    norm_kernel<<<BATCH, 256>>>(targets);
    zero_enc_kernel<<<(BATCH * HH + 255) / 256, 256>>>();
    split_weights<<<G4, 128>>>(w_hh0, w_ih1, w_hh1, w_ih0);

    encoder_kernel<<<ENC_BLOCKS, 512, ENC_SMEM_BYTES>>>(
        w_ih0, w_hh0, b_ih0, b_hh0, w_ih1, w_hh1, b_ih1, b_hh1);

    replicate_kernel<<<NDEC, 256>>>();

    for (int p = 0; p < PSTEPS; p++) {
        int pa = p & 1, pb = pa ^ 1;
        const float* ms_in = (p > 0) ? (musig + (long long)(p - 1) * NDEC * 2) : nullptr;
        const float* ep    = (p > 0) ? (eps + (long long)(p - 1) * NDEC) : nullptr;
        // layer 0: sample prev step + lags + h0 @ w_hh0^T (mat 0)
        dec_cell_bf16<<<dim3(NDEC / DBM, 8), 256, DEC_SMEM_BYTES>>>(
            hist + p + 6, wlag,
            nullptr, nullptr,
            h0d + pa * (NDEC * HH), wsp + 0 * 2 * WLO,
            b_ih0, b_hh0, c0d,
            h0d + pb * (NDEC * HH), c0d,
            ms_in, ep, b_mu, b_sigma, p - 1,
            nullptr, nullptr, nullptr);
        // layer 1: h0_new @ w_ih1^T (mat 1) + h1 @ w_hh1^T (mat 2), fused head
        dec_cell_bf16<<<dim3(NDEC / DBM, 8), 256, DEC_SMEM_BYTES>>>(
            nullptr, nullptr,
            h0d + pb * (NDEC * HH), wsp + 1 * 2 * WLO,
            h1d + pa * (NDEC * HH), wsp + 2 * 2 * WLO,
            b_ih1, b_hh1, c1d,
            h1d + pb * (NDEC * HH), c1d,
            nullptr, nullptr, nullptr, nullptr, 0,
            w_mu, w_sigma, musig + (long long)p * NDEC * 2);
    }

    reduce_kernel<<<(BATCH * PSTEPS * 32 + 255) / 256, 256>>>(out, eps, b_mu, b_sigma);
}

// round 15
// speedup vs baseline: 1.0996x; 1.0996x over previous
#include <cuda_runtime.h>
#include <cuda_bf16.h>
#include <cuda_fp16.h>
#include <cstdint>
#include <math.h>

#define HH      256
#define G4      1024
#define BATCH   256
#define WIN     512
#define TT      519     // W + MAXLAG
#define MAXLAG  7
#define SREP    100
#define NDEC    25600   // BATCH * SREP
#define PSTEPS  24
#define ESTEPS  512
#define ENC_BLOCKS 128

// ---- encoder v4 smem layout (4-byte units) ----
#define WPK    132
#define MATSZ  (2 * 64 * WPK)
#define OFF_CHH (3 * MATSZ)
#define OFF_CHL (OFF_CHH + 1536)
#define OFF_RED (OFF_CHL + 1536)
#define OFF_SXW (OFF_RED + 32 * 68)
#define OFF_SXA (OFF_SXW + 64 * 8)
#define ENC_SMEM_UNITS (OFF_SXA + 32 * 8)
#define ENC_SMEM_BYTES (ENC_SMEM_UNITS * 4)

// ---- decoder dynamic smem (bytes): fp16 2-pass, 2-buffer tiles + bias ----
#define DBM 128
#define DPK 12
#define DTILEU (DBM * DPK)
#define DO_AH  0
#define DO_BH  (2 * DTILEU * 4)
#define DO_BL  (4 * DTILEU * 4)
#define DO_BIAS (6 * DTILEU * 4)
#define DEC_SMEM_BYTES (DO_BIAS + 512)

// ---------------- scratch ----------------
__device__ __align__(128) float g_scaled[BATCH * TT];
__device__ float g_loc[BATCH];
__device__ float g_scale[BATCH];

__device__ __align__(128) float g_h0e[2][BATCH * HH];
__device__ __align__(128) float g_c0e[BATCH * HH];
__device__ __align__(128) float g_h1e[2][BATCH * HH];
__device__ __align__(128) float g_c1e[BATCH * HH];

__device__ __align__(128) float g_h0d[2][NDEC * HH];
__device__ __align__(128) float g_c0d[NDEC * HH];
__device__ __align__(128) float g_h1d[2][NDEC * HH];
__device__ __align__(128) float g_c1d[NDEC * HH];

__device__ __align__(128) float g_hist[NDEC * 32];
__device__ __align__(128) float g_musig[PSTEPS * NDEC * 2];

__device__ unsigned g_ectr = 0;

__device__ __forceinline__ float sigf(float x) { return 1.0f / (1.0f + expf(-x)); }

#define MMA_BF16(c, a, b) \
    asm volatile("mma.sync.aligned.m16n8k16.row.col.f32.bf16.bf16.f32 " \
                 "{%0,%1,%2,%3}, {%4,%5,%6,%7}, {%8,%9}, {%0,%1,%2,%3};\n" \
                 : "+f"((c)[0]), "+f"((c)[1]), "+f"((c)[2]), "+f"((c)[3]) \
                 : "r"((a)[0]), "r"((a)[1]), "r"((a)[2]), "r"((a)[3]), \
                   "r"((b)[0]), "r"((b)[1]))

#define MMA_F16(c, a, b) \
    asm volatile("mma.sync.aligned.m16n8k16.row.col.f32.f16.f16.f32 " \
                 "{%0,%1,%2,%3}, {%4,%5,%6,%7}, {%8,%9}, {%0,%1,%2,%3};\n" \
                 : "+f"((c)[0]), "+f"((c)[1]), "+f"((c)[2]), "+f"((c)[3]) \
                 : "r"((a)[0]), "r"((a)[1]), "r"((a)[2]), "r"((a)[3]), \
                   "r"((b)[0]), "r"((b)[1]))

__device__ __forceinline__ void bsplit2(float x, float y, unsigned& hi, unsigned& lo) {
    __nv_bfloat16 hx = __float2bfloat16(x);
    __nv_bfloat16 hy = __float2bfloat16(y);
    __nv_bfloat162 hp = __halves2bfloat162(hx, hy);
    __nv_bfloat162 lp = __halves2bfloat162(
        __float2bfloat16(x - __bfloat162float(hx)),
        __float2bfloat16(y - __bfloat162float(hy)));
    hi = *reinterpret_cast<unsigned*>(&hp);
    lo = *reinterpret_cast<unsigned*>(&lp);
}

// fp16 split: hi = rn(x); lo = rn(x - hi)
__device__ __forceinline__ void hsplit2(float x, float y, unsigned& hi, unsigned& lo) {
    __half2 hp = __floats2half2_rn(x, y);
    __half2 lp = __floats2half2_rn(x - __low2float(hp), y - __high2float(hp));
    hi = *reinterpret_cast<unsigned*>(&hp);
    lo = *reinterpret_cast<unsigned*>(&lp);
}
__device__ __forceinline__ unsigned hpack2(float x, float y) {
    __half2 hp = __floats2half2_rn(x, y);
    return *reinterpret_cast<unsigned*>(&hp);
}

// ---------------- normalization ----------------
__global__ void norm_kernel(const float* __restrict__ tp) {
    int b = blockIdx.x;
    int tid = threadIdx.x;
    const float* row = tp + b * TT;

    double s = 0.0, q = 0.0;
    for (int j = tid; j < WIN; j += blockDim.x) {
        double v = (double)row[MAXLAG + j];
        s += v; q += v * v;
    }
    __shared__ double ss[256], sq[256];
    ss[tid] = s; sq[tid] = q;
    __syncthreads();
    for (int o = 128; o > 0; o >>= 1) {
        if (tid < o) { ss[tid] += ss[tid + o]; sq[tid] += sq[tid + o]; }
        __syncthreads();
    }
    __shared__ float smean, sscale;
    if (tid == 0) {
        double mean = ss[0] / (double)WIN;
        double var  = sq[0] / (double)WIN - mean * mean;
        if (var < 0.0) var = 0.0;
        float sd = (float)sqrt(var);
        float sc = (sd < 1e-10f) ? 1.0f : sd;
        smean = (float)mean; sscale = sc;
        g_loc[b] = (float)mean; g_scale[b] = sc;
    }
    __syncthreads();
    float m = smean, sc = sscale;
    for (int j = tid; j < TT; j += blockDim.x)
        g_scaled[b * TT + j] = (row[j] - m) / sc;
}

__global__ void zero_enc_kernel() {
    int i = blockIdx.x * blockDim.x + threadIdx.x;
    if (i < BATCH * HH) {
        g_h0e[0][i] = 0.f; g_c0e[i] = 0.f;
        g_h1e[0][i] = 0.f; g_c1e[i] = 0.f;
    }
    if (i == 0) g_ectr = 0;
}

__global__ void zero_musig_kernel() {
    int i = blockIdx.x * blockDim.x + threadIdx.x;
    int n = PSTEPS * NDEC * 2;
    for (; i < n; i += gridDim.x * blockDim.x) g_musig[i] = 0.f;
}

// ---------------- persistent encoder v4 (unchanged from R9/R13 wins) ----------------
__global__ void __launch_bounds__(512) encoder_kernel(
    const float* __restrict__ w_ih0, const float* __restrict__ w_hh0,
    const float* __restrict__ b_ih0, const float* __restrict__ b_hh0,
    const float* __restrict__ w_ih1, const float* __restrict__ w_hh1,
    const float* __restrict__ b_ih1, const float* __restrict__ b_hh1)
{
    extern __shared__ unsigned esu[];
    float* esf = reinterpret_cast<float*>(esu);
    unsigned* W0h  = esu;                 unsigned* W0l  = esu + 64 * WPK;
    unsigned* WI1h = esu + MATSZ;         unsigned* WI1l = esu + MATSZ + 64 * WPK;
    unsigned* WH1h = esu + 2 * MATSZ;     unsigned* WH1l = esu + 2 * MATSZ + 64 * WPK;
    unsigned* CHH  = esu + OFF_CHH;
    unsigned* CHL  = esu + OFF_CHL;
    float* RED = esf + OFF_RED;
    float* SXW = esf + OFF_SXW;
    float* SXA = esf + OFF_SXA;

    const int t    = threadIdx.x;
    const int lane = t & 31;
    const int w    = t >> 5;
    const int grp  = w >> 3;
    const int wl   = w & 7;
    const int m_w  = (wl & 1) * 16;
    const int n_w  = (wl >> 1) * 16;
    const int qr   = lane >> 2;
    const int qc   = lane & 3;
    const int b0   = (blockIdx.x & 7) * 32;
    const int u0   = (blockIdx.x >> 3) * 16;

    for (int i = t; i < 64 * 128; i += 512) {
        int r  = i >> 7;
        int kp = i & 127;
        int grow = u0 + (r & 15) + ((r >> 4) << 8);
        unsigned hi, lo;
        bsplit2(w_hh0[grow * 256 + 2 * kp], w_hh0[grow * 256 + 2 * kp + 1], hi, lo);
        W0h[r * WPK + kp] = hi;  W0l[r * WPK + kp] = lo;
        bsplit2(w_ih1[grow * 256 + 2 * kp], w_ih1[grow * 256 + 2 * kp + 1], hi, lo);
        WI1h[r * WPK + kp] = hi; WI1l[r * WPK + kp] = lo;
        bsplit2(w_hh1[grow * 256 + 2 * kp], w_hh1[grow * 256 + 2 * kp + 1], hi, lo);
        WH1h[r * WPK + kp] = hi; WH1l[r * WPK + kp] = lo;
    }
    if (t < 64) {
        int grow = u0 + (t & 15) + ((t >> 4) << 8);
#pragma unroll
        for (int k = 0; k < 7; k++) SXW[t * 8 + k] = w_ih0[grow * 7 + k];
    }

    const int eul = t & 15;
    const int er  = t >> 4;
    float bI0 = 0, bF0 = 0, bG0 = 0, bO0 = 0, bI1 = 0, bF1 = 0, bG1 = 0, bO1 = 0;
    if (t < 256) {
        int u = u0 + eul;
        bI0 = b_ih0[u]       + b_hh0[u];
        bF0 = b_ih0[u + 256] + b_hh0[u + 256];
        bG0 = b_ih0[u + 512] + b_hh0[u + 512];
        bO0 = b_ih0[u + 768] + b_hh0[u + 768];
        bI1 = b_ih1[u]       + b_hh1[u];
        bF1 = b_ih1[u + 256] + b_hh1[u + 256];
        bG1 = b_ih1[u + 512] + b_hh1[u + 512];
        bO1 = b_ih1[u + 768] + b_hh1[u + 768];
    }
    __syncthreads();

    const int gt   = t & 255;
    const int prow = gt >> 3;
    const int pc   = gt & 7;
    unsigned* CHHg = CHH + grp * 768;
    unsigned* CHLg = CHL + grp * 768;

    auto gemm_tc = [&](const float* act, const unsigned* Wh, const unsigned* Wl,
                       float (&acc)[2][4]) {
        const int kb  = grp * 128;
        const int kpb = grp * 64;
        {
            float2 p = __ldcg((const float2*)(act + (b0 + prow) * HH + kb + pc * 2));
            unsigned hi, lo; bsplit2(p.x, p.y, hi, lo);
            CHHg[prow * 12 + pc] = hi;
            CHLg[prow * 12 + pc] = lo;
        }
        __syncthreads();
        for (int ch = 0; ch < 8; ch++) {
            float2 nxt;
            const bool have = (ch + 1) < 8;
            if (have)
                nxt = __ldcg((const float2*)(act + (b0 + prow) * HH + kb + (ch + 1) * 16 + pc * 2));
            const unsigned* hbh = CHHg + (ch & 1) * 384;
            const unsigned* hbl = CHLg + (ch & 1) * 384;
            unsigned ahi[4], alo[4];
            ahi[0] = hbh[(m_w + qr) * 12 + qc];
            ahi[1] = hbh[(m_w + qr + 8) * 12 + qc];
            ahi[2] = hbh[(m_w + qr) * 12 + qc + 4];
            ahi[3] = hbh[(m_w + qr + 8) * 12 + qc + 4];
            alo[0] = hbl[(m_w + qr) * 12 + qc];
            alo[1] = hbl[(m_w + qr + 8) * 12 + qc];
            alo[2] = hbl[(m_w + qr) * 12 + qc + 4];
            alo[3] = hbl[(m_w + qr + 8) * 12 + qc + 4];
#pragma unroll
            for (int f = 0; f < 2; f++) {
                int wr  = (n_w + f * 8 + qr) * WPK + kpb + ch * 8;
                unsigned bhi[2] = {Wh[wr + qc], Wh[wr + qc + 4]};
                unsigned blo[2] = {Wl[wr + qc], Wl[wr + qc + 4]};
                MMA_BF16(acc[f], ahi, bhi);
                MMA_BF16(acc[f], ahi, blo);
                MMA_BF16(acc[f], alo, bhi);
            }
            if (have) {
                unsigned hi, lo; bsplit2(nxt.x, nxt.y, hi, lo);
                CHHg[((ch + 1) & 1) * 384 + prow * 12 + pc] = hi;
                CHLg[((ch + 1) & 1) * 384 + prow * 12 + pc] = lo;
            }
            __syncthreads();
        }
    };

    auto reduce_store = [&](float (&acc)[2][4]) {
        if (grp == 1) {
#pragma unroll
            for (int f = 0; f < 2; f++)
#pragma unroll
                for (int half = 0; half < 2; half++)
#pragma unroll
                    for (int j = 0; j < 2; j++)
                        RED[(m_w + qr + half * 8) * 68 + n_w + f * 8 + 2 * qc + j] =
                            acc[f][half * 2 + j];
        }
        __syncthreads();
        if (grp == 0) {
#pragma unroll
            for (int f = 0; f < 2; f++)
#pragma unroll
                for (int half = 0; half < 2; half++)
#pragma unroll
                    for (int j = 0; j < 2; j++)
                        RED[(m_w + qr + half * 8) * 68 + n_w + f * 8 + 2 * qc + j] +=
                            acc[f][half * 2 + j];
        }
        __syncthreads();
    };

    for (int step = 0; step < ESTEPS; step++) {
        const int pa = step & 1, pb = pa ^ 1;
        float* h0b = g_h0e[pb];
        float* h1b = g_h1e[pb];

        if (t < 32) {
            const float* xr = g_scaled + (b0 + t) * TT + step + 6;
#pragma unroll
            for (int k = 0; k < 7; k++) SXA[t * 8 + k] = xr[-k];
        }

        float acc[2][4];
#pragma unroll
        for (int f = 0; f < 2; f++)
#pragma unroll
            for (int r = 0; r < 4; r++) acc[f][r] = 0.f;

        gemm_tc(g_h0e[pa], W0h, W0l, acc);
        reduce_store(acc);

        if (t < 256) {
#pragma unroll
            for (int h2 = 0; h2 < 2; h2++) {
                int r = er + 16 * h2;
                float gi = RED[r * 68 + eul]      + bI0;
                float gf = RED[r * 68 + 16 + eul] + bF0;
                float gg = RED[r * 68 + 32 + eul] + bG0;
                float go = RED[r * 68 + 48 + eul] + bO0;
#pragma unroll
                for (int k = 0; k < 7; k++) {
                    float x = SXA[r * 8 + k];
                    gi = fmaf(x, SXW[eul * 8 + k], gi);
                    gf = fmaf(x, SXW[(16 + eul) * 8 + k], gf);
                    gg = fmaf(x, SXW[(32 + eul) * 8 + k], gg);
                    go = fmaf(x, SXW[(48 + eul) * 8 + k], go);
                }
                int idx = (b0 + r) * HH + (u0 + eul);
                float c = g_c0e[idx];
                float cn = sigf(gf) * c + sigf(gi) * tanhf(gg);
                g_c0e[idx] = cn;
                h0b[idx] = sigf(go) * tanhf(cn);
            }
        }
        __syncthreads();
        if (t == 0) { __threadfence(); atomicAdd(&g_ectr, 1u); }

#pragma unroll
        for (int f = 0; f < 2; f++)
#pragma unroll
            for (int r = 0; r < 4; r++) acc[f][r] = 0.f;

        if (t == 0) {
            unsigned tgt = 256u * (unsigned)step;
            while (*(volatile unsigned*)&g_ectr < tgt) { }
        }
        __syncthreads();
        gemm_tc(g_h1e[pa], WH1h, WH1l, acc);

        if (t == 0) {
            unsigned tgt = 256u * (unsigned)step + 128u;
            while (*(volatile unsigned*)&g_ectr < tgt) { }
        }
        __syncthreads();
        gemm_tc(h0b, WI1h, WI1l, acc);

        reduce_store(acc);

        if (t < 256) {
#pragma unroll
            for (int h2 = 0; h2 < 2; h2++) {
                int r = er + 16 * h2;
                float gi = RED[r * 68 + eul]      + bI1;
                float gf = RED[r * 68 + 16 + eul] + bF1;
                float gg = RED[r * 68 + 32 + eul] + bG1;
                float go = RED[r * 68 + 48 + eul] + bO1;
                int idx = (b0 + r) * HH + (u0 + eul);
                float c = g_c1e[idx];
                float cn = sigf(gf) * c + sigf(gi) * tanhf(gg);
                g_c1e[idx] = cn;
                h1b[idx] = sigf(go) * tanhf(cn);
            }
        }
        __syncthreads();
        if (t == 0) { __threadfence(); atomicAdd(&g_ectr, 1u); }
    }
}

// ---------------- decoder cell v8: fp16 2-pass (A-hi only), fused head ----------------
__global__ void __launch_bounds__(256) dec_cell_f16(
    const float* __restrict__ xs,        // lag base (g_hist + p + 6) or null
    const float* __restrict__ w_ihs,     // (1024,7)
    const float* __restrict__ xb,        // big x (N,256) or null
    const float* __restrict__ w_ihb,     // (1024,256)
    const float* __restrict__ h_in,      // (N,256)
    const float* __restrict__ w_hh,      // (1024,256)
    const float* __restrict__ b_ih, const float* __restrict__ b_hh,
    const float* __restrict__ c_in,
    float* __restrict__ h_out, float* __restrict__ c_out,
    // layer-0 sampling prologue (p>0):
    const float* __restrict__ musig_in, const float* __restrict__ eps_prev,
    const float* __restrict__ b_mu, const float* __restrict__ b_sig, int pm1,
    // layer-1 head partials:
    const float* __restrict__ w_mu, const float* __restrict__ w_sig,
    float* __restrict__ musig_out)
{
    extern __shared__ __align__(128) char dsm[];
    unsigned* tAhi = (unsigned*)(dsm + DO_AH);
    unsigned* tBhi = (unsigned*)(dsm + DO_BH);
    unsigned* tBlo = (unsigned*)(dsm + DO_BL);
    float* sBias = (float*)(dsm + DO_BIAS);

    const int t    = threadIdx.x;
    const int lane = t & 31;
    const int wid  = t >> 5;
    const int m0w  = (wid & 1) * 64;
    const int u0w  = (wid >> 1) * 8;
    const int b0   = blockIdx.x * DBM;
    const int u0   = blockIdx.y * 32;

    const int lrow = t >> 1;
    const int lc0  = (t & 1) * 8;
    const int lp0  = (t & 1) * 4;
    const int lgrow = u0 + (lrow & 31) + ((lrow >> 5) << 8);

    if (t < 128) {
        int grow = u0 + (t & 31) + ((t >> 5) << 8);
        sBias[t] = b_ih[grow] + b_hh[grow];
    }

    // ---- layer-0 prologue: materialize previous step's sample into hist ----
    if (musig_in != nullptr) {
        if (t < DBM) {
            int row = b0 + t;
            float mu = musig_in[row * 2]     + b_mu[0];
            float sg = musig_in[row * 2 + 1] + b_sig[0];
            float sp = (sg > 20.f) ? sg : log1pf(expf(sg));
            g_hist[row * 32 + MAXLAG + pm1] = mu + sp * eps_prev[row];
        }
        __syncthreads();
    }

    float acc[4][4][4];
#pragma unroll
    for (int mi = 0; mi < 4; mi++)
#pragma unroll
        for (int g = 0; g < 4; g++)
#pragma unroll
            for (int r = 0; r < 4; r++) acc[mi][g][r] = 0.f;

    const int qr = lane >> 2;
    const int qc = lane & 3;

    auto compute_chunk = [&](int buf) {
        const unsigned* AH = tAhi + buf * DTILEU;
        const unsigned* BH = tBhi + buf * DTILEU;
        const unsigned* BL = tBlo + buf * DTILEU;
        unsigned ahi[4][4];
#pragma unroll
        for (int mi = 0; mi < 4; mi++) {
            int r = m0w + mi * 16 + qr;
            ahi[mi][0] = AH[r * DPK + qc];       ahi[mi][1] = AH[(r + 8) * DPK + qc];
            ahi[mi][2] = AH[r * DPK + qc + 4];   ahi[mi][3] = AH[(r + 8) * DPK + qc + 4];
        }
        unsigned bhi[4][2], blo[4][2];
#pragma unroll
        for (int g = 0; g < 4; g++) {
            int br = g * 32 + u0w + qr;
            bhi[g][0] = BH[br * DPK + qc]; bhi[g][1] = BH[br * DPK + qc + 4];
            blo[g][0] = BL[br * DPK + qc]; blo[g][1] = BL[br * DPK + qc + 4];
        }
#pragma unroll
        for (int mi = 0; mi < 4; mi++)
#pragma unroll
            for (int g = 0; g < 4; g++) {
                MMA_F16(acc[mi][g], ahi[mi], bhi[g]);
                MMA_F16(acc[mi][g], ahi[mi], blo[g]);
            }
    };

    auto store_a8 = [&](int buf, const float* v) {
        unsigned hi[4];
#pragma unroll
        for (int j = 0; j < 4; j++) hi[j] = hpack2(v[2 * j], v[2 * j + 1]);
        *(uint4*)(tAhi + buf * DTILEU + lrow * DPK + lp0) = make_uint4(hi[0], hi[1], hi[2], hi[3]);
    };
    auto store_b8 = [&](int buf, const float* v) {
        unsigned hi[4], lo[4];
#pragma unroll
        for (int j = 0; j < 4; j++) hsplit2(v[2 * j], v[2 * j + 1], hi[j], lo[j]);
        *(uint4*)(tBhi + buf * DTILEU + lrow * DPK + lp0) = make_uint4(hi[0], hi[1], hi[2], hi[3]);
        *(uint4*)(tBlo + buf * DTILEU + lrow * DPK + lp0) = make_uint4(lo[0], lo[1], lo[2], lo[3]);
    };

    int tb = 0;

    // -------- lag chunk (K=7 zero-padded to 16) --------
    if (xs != nullptr) {
        float va[8], vb[8];
#pragma unroll
        for (int cc = 0; cc < 8; cc++) {
            int k = lc0 + cc;
            va[cc] = (k < 7) ? xs[(b0 + lrow) * 32 - k] : 0.f;
            vb[cc] = (k < 7) ? w_ihs[lgrow * 7 + k] : 0.f;
        }
        store_a8(tb, va);
        store_b8(tb, vb);
        __syncthreads();
        compute_chunk(tb);
        tb ^= 1;
    }

    // -------- dense K=256 segments: one sync per chunk --------
    auto gemm_segment = [&](const float* __restrict__ act, const float* __restrict__ wgt) {
        for (int k0 = 0; k0 < HH; k0 += 16) {
            float av[8], wv[8];
            *(float4*)(av)     = *(const float4*)(act + (long long)(b0 + lrow) * HH + k0 + lc0);
            *(float4*)(av + 4) = *(const float4*)(act + (long long)(b0 + lrow) * HH + k0 + lc0 + 4);
            *(float4*)(wv)     = *(const float4*)(wgt + (long long)lgrow * HH + k0 + lc0);
            *(float4*)(wv + 4) = *(const float4*)(wgt + (long long)lgrow * HH + k0 + lc0 + 4);
            store_a8(tb, av);
            store_b8(tb, wv);
            __syncthreads();
            compute_chunk(tb);
            tb ^= 1;
        }
    };

    if (xb != nullptr) gemm_segment(xb, w_ihb);
    gemm_segment(h_in, w_hh);

    // -------- epilogue: fused LSTM + optional head partials --------
    float wmu[2] = {0.f, 0.f}, wsg[2] = {0.f, 0.f};
    if (w_mu != nullptr) {
#pragma unroll
        for (int j = 0; j < 2; j++) {
            int u = u0 + u0w + 2 * qc + j;
            wmu[j] = w_mu[u];
            wsg[j] = w_sig[u];
        }
    }
#pragma unroll
    for (int mi = 0; mi < 4; mi++) {
        int rbase = b0 + m0w + mi * 16 + qr;
#pragma unroll
        for (int half = 0; half < 2; half++) {
            int row = rbase + half * 8;
            float hn2[2];
#pragma unroll
            for (int j = 0; j < 2; j++) {
                int ucol = 2 * qc + j;
                int u = u0 + u0w + ucol;
                int ci = half * 2 + j;
                float gi_ = acc[mi][0][ci] + sBias[ 0 + u0w + ucol];
                float gf  = acc[mi][1][ci] + sBias[32 + u0w + ucol];
                float gg  = acc[mi][2][ci] + sBias[64 + u0w + ucol];
                float go  = acc[mi][3][ci] + sBias[96 + u0w + ucol];
                long long idx = (long long)row * HH + u;
                float c = c_in[idx];
                float cn = sigf(gf) * c + sigf(gi_) * tanhf(gg);
                float hn = sigf(go) * tanhf(cn);
                c_out[idx] = cn;
                h_out[idx] = hn;
                hn2[j] = hn;
            }
            if (w_mu != nullptr) {
                float pm = hn2[0] * wmu[0] + hn2[1] * wmu[1];
                float ps = hn2[0] * wsg[0] + hn2[1] * wsg[1];
                pm += __shfl_xor_sync(0xffffffffu, pm, 1);
                ps += __shfl_xor_sync(0xffffffffu, ps, 1);
                pm += __shfl_xor_sync(0xffffffffu, pm, 2);
                ps += __shfl_xor_sync(0xffffffffu, ps, 2);
                if (qc == 0) {
                    atomicAdd(&musig_out[(long long)row * 2],     pm);
                    atomicAdd(&musig_out[(long long)row * 2 + 1], ps);
                }
            }
        }
    }
}

// ---------------- replicate encoder state x100 + init history ----------------
__global__ void replicate_kernel() {
    int row = blockIdx.x;
    int u   = threadIdx.x;
    int b   = row / SREP;
    long long d = (long long)row * HH + u;
    long long s = (long long)b * HH + u;
    g_h0d[0][d] = g_h0e[0][s];
    g_c0d[d]    = g_c0e[s];
    g_h1d[0][d] = g_h1e[0][s];
    g_c1d[d]    = g_c1e[s];
    if (u < MAXLAG) g_hist[row * 32 + u] = g_scaled[b * TT + WIN + u];
}

// ---------------- mean over samples (from musig) + denormalize ----------------
__global__ void reduce_kernel(float* __restrict__ out,
                              const float* __restrict__ eps,
                              const float* __restrict__ b_mu,
                              const float* __restrict__ b_sig) {
    int gid  = blockIdx.x * blockDim.x + threadIdx.x;
    int warp = gid >> 5;
    int lane = gid & 31;
    if (warp >= BATCH * PSTEPS) return;
    int b = warp / PSTEPS;
    int p = warp % PSTEPS;
    const float bmu = b_mu[0], bsg = b_sig[0];
    float s = 0.f;
    for (int ss = lane; ss < SREP; ss += 32) {
        long long row = (long long)b * SREP + ss;
        const float* ms = g_musig + ((long long)p * NDEC + row) * 2;
        float mu = ms[0] + bmu;
        float sg = ms[1] + bsg;
        float sp = (sg > 20.f) ? sg : log1pf(expf(sg));
        s += mu + sp * eps[(long long)p * NDEC + row];
    }
#pragma unroll
    for (int o = 16; o > 0; o >>= 1) s += __shfl_xor_sync(0xffffffffu, s, o);
    if (lane == 0)
        out[b * PSTEPS + p] = s * (1.0f / (float)SREP) * g_scale[b] + g_loc[b];
}

// ---------------- launch ----------------
extern "C" void kernel_launch(void* const* d_in, const int* in_sizes, int n_in,
                              void* d_out, int out_size) {
    const float* targets = (const float*)d_in[0];
    const float* w_ih0   = (const float*)d_in[1];
    const float* w_hh0   = (const float*)d_in[2];
    const float* b_ih0   = (const float*)d_in[3];
    const float* b_hh0   = (const float*)d_in[4];
    const float* w_ih1   = (const float*)d_in[5];
    const float* w_hh1   = (const float*)d_in[6];
    const float* b_ih1   = (const float*)d_in[7];
    const float* b_hh1   = (const float*)d_in[8];
    const float* w_mu    = (const float*)d_in[9];
    const float* b_mu    = (const float*)d_in[10];
    const float* w_sigma = (const float*)d_in[11];
    const float* b_sigma = (const float*)d_in[12];
    const float* eps     = (const float*)d_in[13];
    float* out = (float*)d_out;

    float *h0d, *c0d, *h1d, *c1d, *hist, *musig;
    cudaGetSymbolAddress((void**)&h0d, g_h0d);
    cudaGetSymbolAddress((void**)&c0d, g_c0d);
    cudaGetSymbolAddress((void**)&h1d, g_h1d);
    cudaGetSymbolAddress((void**)&c1d, g_c1d);
    cudaGetSymbolAddress((void**)&hist, g_hist);
    cudaGetSymbolAddress((void**)&musig, g_musig);

    cudaFuncSetAttribute(encoder_kernel,
                         cudaFuncAttributeMaxDynamicSharedMemorySize, ENC_SMEM_BYTES);
    cudaFuncSetAttribute(dec_cell_f16,
                         cudaFuncAttributeMaxDynamicSharedMemorySize, DEC_SMEM_BYTES);

    norm_kernel<<<BATCH, 256>>>(targets);
    zero_enc_kernel<<<(BATCH * HH + 255) / 256, 256>>>();
    zero_musig_kernel<<<1024, 256>>>();

    encoder_kernel<<<ENC_BLOCKS, 512, ENC_SMEM_BYTES>>>(
        w_ih0, w_hh0, b_ih0, b_hh0, w_ih1, w_hh1, b_ih1, b_hh1);

    replicate_kernel<<<NDEC, 256>>>();

    for (int p = 0; p < PSTEPS; p++) {
        int pa = p & 1, pb = pa ^ 1;
        const float* ms_in = (p > 0) ? (musig + (long long)(p - 1) * NDEC * 2) : nullptr;
        const float* ep    = (p > 0) ? (eps + (long long)(p - 1) * NDEC) : nullptr;
        // layer 0: sample prev step + lags + h0 @ w_hh0^T
        dec_cell_f16<<<dim3(NDEC / DBM, 8), 256, DEC_SMEM_BYTES>>>(
            hist + p + 6, w_ih0,
            nullptr, nullptr,
            h0d + pa * (NDEC * HH), w_hh0, b_ih0, b_hh0,
            c0d, h0d + pb * (NDEC * HH), c0d,
            ms_in, ep, b_mu, b_sigma, p - 1,
            nullptr, nullptr, nullptr);
        // layer 1: h0_new @ w_ih1^T + h1 @ w_hh1^T, fused head partials
        dec_cell_f16<<<dim3(NDEC / DBM, 8), 256, DEC_SMEM_BYTES>>>(
            nullptr, nullptr,
            h0d + pb * (NDEC * HH), w_ih1,
            h1d + pa * (NDEC * HH), w_hh1, b_ih1, b_hh1,
            c1d, h1d + pb * (NDEC * HH), c1d,
            nullptr, nullptr, nullptr, nullptr, 0,
            w_mu, w_sigma, musig + (long long)p * NDEC * 2);
    }

    reduce_kernel<<<(BATCH * PSTEPS * 32 + 255) / 256, 256>>>(out, eps, b_mu, b_sigma);
}

// round 16
// speedup vs baseline: 1.3431x; 1.2214x over previous
#include <cuda_runtime.h>
#include <cuda_bf16.h>
#include <cuda_fp16.h>
#include <cstdint>
#include <math.h>

#define HH      256
#define HP      128     // packed half2 per row
#define G4      1024
#define BATCH   256
#define WIN     512
#define TT      519     // W + MAXLAG
#define MAXLAG  7
#define SREP    100
#define NDEC    25600   // BATCH * SREP
#define PSTEPS  24
#define ESTEPS  512
#define ENC_BLOCKS 128

// ---- encoder v4 smem layout (4-byte units) ----
#define WPK    132
#define MATSZ  (2 * 64 * WPK)
#define OFF_CHH (3 * MATSZ)
#define OFF_CHL (OFF_CHH + 1536)
#define OFF_RED (OFF_CHL + 1536)
#define OFF_SXW (OFF_RED + 32 * 68)
#define OFF_SXA (OFF_SXW + 64 * 8)
#define ENC_SMEM_UNITS (OFF_SXA + 32 * 8)
#define ENC_SMEM_BYTES (ENC_SMEM_UNITS * 4)

// ---- decoder dynamic smem (bytes): fp16 1-pass, 2-buffer tiles + bias ----
#define DBM 128
#define DPK 12
#define DTILEU (DBM * DPK)
#define DO_AH  0
#define DO_BH  (2 * DTILEU * 4)
#define DO_BIAS (4 * DTILEU * 4)
#define DEC_SMEM_BYTES (DO_BIAS + 512)

// ---------------- scratch ----------------
__device__ __align__(128) float g_scaled[BATCH * TT];
__device__ float g_loc[BATCH];
__device__ float g_scale[BATCH];

__device__ __align__(128) float g_h0e[2][BATCH * HH];
__device__ __align__(128) float g_c0e[BATCH * HH];
__device__ __align__(128) float g_h1e[2][BATCH * HH];
__device__ __align__(128) float g_c1e[BATCH * HH];

// decoder h state: packed fp16 (half2 as unsigned), c fp32
__device__ __align__(128) unsigned g_h0d[2][NDEC * HP];
__device__ __align__(128) unsigned g_h1d[2][NDEC * HP];
__device__ __align__(128) float g_c0d[NDEC * HH];
__device__ __align__(128) float g_c1d[NDEC * HH];

__device__ __align__(128) float g_hist[NDEC * 32];
__device__ __align__(128) float g_musig[PSTEPS * NDEC * 2];

__device__ unsigned g_ectr = 0;

__device__ __forceinline__ float sigf(float x) { return 1.0f / (1.0f + expf(-x)); }

#define MMA_BF16(c, a, b) \
    asm volatile("mma.sync.aligned.m16n8k16.row.col.f32.bf16.bf16.f32 " \
                 "{%0,%1,%2,%3}, {%4,%5,%6,%7}, {%8,%9}, {%0,%1,%2,%3};\n" \
                 : "+f"((c)[0]), "+f"((c)[1]), "+f"((c)[2]), "+f"((c)[3]) \
                 : "r"((a)[0]), "r"((a)[1]), "r"((a)[2]), "r"((a)[3]), \
                   "r"((b)[0]), "r"((b)[1]))

#define MMA_F16(c, a, b) \
    asm volatile("mma.sync.aligned.m16n8k16.row.col.f32.f16.f16.f32 " \
                 "{%0,%1,%2,%3}, {%4,%5,%6,%7}, {%8,%9}, {%0,%1,%2,%3};\n" \
                 : "+f"((c)[0]), "+f"((c)[1]), "+f"((c)[2]), "+f"((c)[3]) \
                 : "r"((a)[0]), "r"((a)[1]), "r"((a)[2]), "r"((a)[3]), \
                   "r"((b)[0]), "r"((b)[1]))

__device__ __forceinline__ void bsplit2(float x, float y, unsigned& hi, unsigned& lo) {
    __nv_bfloat16 hx = __float2bfloat16(x);
    __nv_bfloat16 hy = __float2bfloat16(y);
    __nv_bfloat162 hp = __halves2bfloat162(hx, hy);
    __nv_bfloat162 lp = __halves2bfloat162(
        __float2bfloat16(x - __bfloat162float(hx)),
        __float2bfloat16(y - __bfloat162float(hy)));
    hi = *reinterpret_cast<unsigned*>(&hp);
    lo = *reinterpret_cast<unsigned*>(&lp);
}

__device__ __forceinline__ unsigned hpack2(float x, float y) {
    __half2 hp = __floats2half2_rn(x, y);
    return *reinterpret_cast<unsigned*>(&hp);
}

// ---------------- normalization ----------------
__global__ void norm_kernel(const float* __restrict__ tp) {
    int b = blockIdx.x;
    int tid = threadIdx.x;
    const float* row = tp + b * TT;

    double s = 0.0, q = 0.0;
    for (int j = tid; j < WIN; j += blockDim.x) {
        double v = (double)row[MAXLAG + j];
        s += v; q += v * v;
    }
    __shared__ double ss[256], sq[256];
    ss[tid] = s; sq[tid] = q;
    __syncthreads();
    for (int o = 128; o > 0; o >>= 1) {
        if (tid < o) { ss[tid] += ss[tid + o]; sq[tid] += sq[tid + o]; }
        __syncthreads();
    }
    __shared__ float smean, sscale;
    if (tid == 0) {
        double mean = ss[0] / (double)WIN;
        double var  = sq[0] / (double)WIN - mean * mean;
        if (var < 0.0) var = 0.0;
        float sd = (float)sqrt(var);
        float sc = (sd < 1e-10f) ? 1.0f : sd;
        smean = (float)mean; sscale = sc;
        g_loc[b] = (float)mean; g_scale[b] = sc;
    }
    __syncthreads();
    float m = smean, sc = sscale;
    for (int j = tid; j < TT; j += blockDim.x)
        g_scaled[b * TT + j] = (row[j] - m) / sc;
}

__global__ void zero_enc_kernel() {
    int i = blockIdx.x * blockDim.x + threadIdx.x;
    if (i < BATCH * HH) {
        g_h0e[0][i] = 0.f; g_c0e[i] = 0.f;
        g_h1e[0][i] = 0.f; g_c1e[i] = 0.f;
    }
    if (i == 0) g_ectr = 0;
}

__global__ void zero_musig_kernel() {
    int i = blockIdx.x * blockDim.x + threadIdx.x;
    int n = PSTEPS * NDEC * 2;
    for (; i < n; i += gridDim.x * blockDim.x) g_musig[i] = 0.f;
}

// ---------------- persistent encoder v4 (unchanged from R9/R13 wins) ----------------
__global__ void __launch_bounds__(512) encoder_kernel(
    const float* __restrict__ w_ih0, const float* __restrict__ w_hh0,
    const float* __restrict__ b_ih0, const float* __restrict__ b_hh0,
    const float* __restrict__ w_ih1, const float* __restrict__ w_hh1,
    const float* __restrict__ b_ih1, const float* __restrict__ b_hh1)
{
    extern __shared__ unsigned esu[];
    float* esf = reinterpret_cast<float*>(esu);
    unsigned* W0h  = esu;                 unsigned* W0l  = esu + 64 * WPK;
    unsigned* WI1h = esu + MATSZ;         unsigned* WI1l = esu + MATSZ + 64 * WPK;
    unsigned* WH1h = esu + 2 * MATSZ;     unsigned* WH1l = esu + 2 * MATSZ + 64 * WPK;
    unsigned* CHH  = esu + OFF_CHH;
    unsigned* CHL  = esu + OFF_CHL;
    float* RED = esf + OFF_RED;
    float* SXW = esf + OFF_SXW;
    float* SXA = esf + OFF_SXA;

    const int t    = threadIdx.x;
    const int lane = t & 31;
    const int w    = t >> 5;
    const int grp  = w >> 3;
    const int wl   = w & 7;
    const int m_w  = (wl & 1) * 16;
    const int n_w  = (wl >> 1) * 16;
    const int qr   = lane >> 2;
    const int qc   = lane & 3;
    const int b0   = (blockIdx.x & 7) * 32;
    const int u0   = (blockIdx.x >> 3) * 16;

    for (int i = t; i < 64 * 128; i += 512) {
        int r  = i >> 7;
        int kp = i & 127;
        int grow = u0 + (r & 15) + ((r >> 4) << 8);
        unsigned hi, lo;
        bsplit2(w_hh0[grow * 256 + 2 * kp], w_hh0[grow * 256 + 2 * kp + 1], hi, lo);
        W0h[r * WPK + kp] = hi;  W0l[r * WPK + kp] = lo;
        bsplit2(w_ih1[grow * 256 + 2 * kp], w_ih1[grow * 256 + 2 * kp + 1], hi, lo);
        WI1h[r * WPK + kp] = hi; WI1l[r * WPK + kp] = lo;
        bsplit2(w_hh1[grow * 256 + 2 * kp], w_hh1[grow * 256 + 2 * kp + 1], hi, lo);
        WH1h[r * WPK + kp] = hi; WH1l[r * WPK + kp] = lo;
    }
    if (t < 64) {
        int grow = u0 + (t & 15) + ((t >> 4) << 8);
#pragma unroll
        for (int k = 0; k < 7; k++) SXW[t * 8 + k] = w_ih0[grow * 7 + k];
    }

    const int eul = t & 15;
    const int er  = t >> 4;
    float bI0 = 0, bF0 = 0, bG0 = 0, bO0 = 0, bI1 = 0, bF1 = 0, bG1 = 0, bO1 = 0;
    if (t < 256) {
        int u = u0 + eul;
        bI0 = b_ih0[u]       + b_hh0[u];
        bF0 = b_ih0[u + 256] + b_hh0[u + 256];
        bG0 = b_ih0[u + 512] + b_hh0[u + 512];
        bO0 = b_ih0[u + 768] + b_hh0[u + 768];
        bI1 = b_ih1[u]       + b_hh1[u];
        bF1 = b_ih1[u + 256] + b_hh1[u + 256];
        bG1 = b_ih1[u + 512] + b_hh1[u + 512];
        bO1 = b_ih1[u + 768] + b_hh1[u + 768];
    }
    __syncthreads();

    const int gt   = t & 255;
    const int prow = gt >> 3;
    const int pc   = gt & 7;
    unsigned* CHHg = CHH + grp * 768;
    unsigned* CHLg = CHL + grp * 768;

    auto gemm_tc = [&](const float* act, const unsigned* Wh, const unsigned* Wl,
                       float (&acc)[2][4]) {
        const int kb  = grp * 128;
        const int kpb = grp * 64;
        {
            float2 p = __ldcg((const float2*)(act + (b0 + prow) * HH + kb + pc * 2));
            unsigned hi, lo; bsplit2(p.x, p.y, hi, lo);
            CHHg[prow * 12 + pc] = hi;
            CHLg[prow * 12 + pc] = lo;
        }
        __syncthreads();
        for (int ch = 0; ch < 8; ch++) {
            float2 nxt;
            const bool have = (ch + 1) < 8;
            if (have)
                nxt = __ldcg((const float2*)(act + (b0 + prow) * HH + kb + (ch + 1) * 16 + pc * 2));
            const unsigned* hbh = CHHg + (ch & 1) * 384;
            const unsigned* hbl = CHLg + (ch & 1) * 384;
            unsigned ahi[4], alo[4];
            ahi[0] = hbh[(m_w + qr) * 12 + qc];
            ahi[1] = hbh[(m_w + qr + 8) * 12 + qc];
            ahi[2] = hbh[(m_w + qr) * 12 + qc + 4];
            ahi[3] = hbh[(m_w + qr + 8) * 12 + qc + 4];
            alo[0] = hbl[(m_w + qr) * 12 + qc];
            alo[1] = hbl[(m_w + qr + 8) * 12 + qc];
            alo[2] = hbl[(m_w + qr) * 12 + qc + 4];
            alo[3] = hbl[(m_w + qr + 8) * 12 + qc + 4];
#pragma unroll
            for (int f = 0; f < 2; f++) {
                int wr  = (n_w + f * 8 + qr) * WPK + kpb + ch * 8;
                unsigned bhi[2] = {Wh[wr + qc], Wh[wr + qc + 4]};
                unsigned blo[2] = {Wl[wr + qc], Wl[wr + qc + 4]};
                MMA_BF16(acc[f], ahi, bhi);
                MMA_BF16(acc[f], ahi, blo);
                MMA_BF16(acc[f], alo, bhi);
            }
            if (have) {
                unsigned hi, lo; bsplit2(nxt.x, nxt.y, hi, lo);
                CHHg[((ch + 1) & 1) * 384 + prow * 12 + pc] = hi;
                CHLg[((ch + 1) & 1) * 384 + prow * 12 + pc] = lo;
            }
            __syncthreads();
        }
    };

    auto reduce_store = [&](float (&acc)[2][4]) {
        if (grp == 1) {
#pragma unroll
            for (int f = 0; f < 2; f++)
#pragma unroll
                for (int half = 0; half < 2; half++)
#pragma unroll
                    for (int j = 0; j < 2; j++)
                        RED[(m_w + qr + half * 8) * 68 + n_w + f * 8 + 2 * qc + j] =
                            acc[f][half * 2 + j];
        }
        __syncthreads();
        if (grp == 0) {
#pragma unroll
            for (int f = 0; f < 2; f++)
#pragma unroll
                for (int half = 0; half < 2; half++)
#pragma unroll
                    for (int j = 0; j < 2; j++)
                        RED[(m_w + qr + half * 8) * 68 + n_w + f * 8 + 2 * qc + j] +=
                            acc[f][half * 2 + j];
        }
        __syncthreads();
    };

    for (int step = 0; step < ESTEPS; step++) {
        const int pa = step & 1, pb = pa ^ 1;
        float* h0b = g_h0e[pb];
        float* h1b = g_h1e[pb];

        if (t < 32) {
            const float* xr = g_scaled + (b0 + t) * TT + step + 6;
#pragma unroll
            for (int k = 0; k < 7; k++) SXA[t * 8 + k] = xr[-k];
        }

        float acc[2][4];
#pragma unroll
        for (int f = 0; f < 2; f++)
#pragma unroll
            for (int r = 0; r < 4; r++) acc[f][r] = 0.f;

        gemm_tc(g_h0e[pa], W0h, W0l, acc);
        reduce_store(acc);

        if (t < 256) {
#pragma unroll
            for (int h2 = 0; h2 < 2; h2++) {
                int r = er + 16 * h2;
                float gi = RED[r * 68 + eul]      + bI0;
                float gf = RED[r * 68 + 16 + eul] + bF0;
                float gg = RED[r * 68 + 32 + eul] + bG0;
                float go = RED[r * 68 + 48 + eul] + bO0;
#pragma unroll
                for (int k = 0; k < 7; k++) {
                    float x = SXA[r * 8 + k];
                    gi = fmaf(x, SXW[eul * 8 + k], gi);
                    gf = fmaf(x, SXW[(16 + eul) * 8 + k], gf);
                    gg = fmaf(x, SXW[(32 + eul) * 8 + k], gg);
                    go = fmaf(x, SXW[(48 + eul) * 8 + k], go);
                }
                int idx = (b0 + r) * HH + (u0 + eul);
                float c = g_c0e[idx];
                float cn = sigf(gf) * c + sigf(gi) * tanhf(gg);
                g_c0e[idx] = cn;
                h0b[idx] = sigf(go) * tanhf(cn);
            }
        }
        __syncthreads();
        if (t == 0) { __threadfence(); atomicAdd(&g_ectr, 1u); }

#pragma unroll
        for (int f = 0; f < 2; f++)
#pragma unroll
            for (int r = 0; r < 4; r++) acc[f][r] = 0.f;

        if (t == 0) {
            unsigned tgt = 256u * (unsigned)step;
            while (*(volatile unsigned*)&g_ectr < tgt) { }
        }
        __syncthreads();
        gemm_tc(g_h1e[pa], WH1h, WH1l, acc);

        if (t == 0) {
            unsigned tgt = 256u * (unsigned)step + 128u;
            while (*(volatile unsigned*)&g_ectr < tgt) { }
        }
        __syncthreads();
        gemm_tc(h0b, WI1h, WI1l, acc);

        reduce_store(acc);

        if (t < 256) {
#pragma unroll
            for (int h2 = 0; h2 < 2; h2++) {
                int r = er + 16 * h2;
                float gi = RED[r * 68 + eul]      + bI1;
                float gf = RED[r * 68 + 16 + eul] + bF1;
                float gg = RED[r * 68 + 32 + eul] + bG1;
                float go = RED[r * 68 + 48 + eul] + bO1;
                int idx = (b0 + r) * HH + (u0 + eul);
                float c = g_c1e[idx];
                float cn = sigf(gf) * c + sigf(gi) * tanhf(gg);
                g_c1e[idx] = cn;
                h1b[idx] = sigf(go) * tanhf(cn);
            }
        }
        __syncthreads();
        if (t == 0) { __threadfence(); atomicAdd(&g_ectr, 1u); }
    }
}

// ---------------- decoder cell v9: fp16 1-pass, fp16 h state, fused head ----------------
__global__ void __launch_bounds__(256) dec_cell_f16(
    const float* __restrict__ xs,          // lag base (g_hist + p + 6) or null
    const float* __restrict__ w_ihs,       // (1024,7)
    const unsigned* __restrict__ xb,       // big x packed fp16 (N,128) or null
    const float* __restrict__ w_ihb,       // (1024,256)
    const unsigned* __restrict__ h_in,     // packed fp16 (N,128)
    const float* __restrict__ w_hh,        // (1024,256)
    const float* __restrict__ b_ih, const float* __restrict__ b_hh,
    const float* __restrict__ c_in,
    unsigned* __restrict__ h_out, float* __restrict__ c_out,
    // layer-0 sampling prologue (p>0):
    const float* __restrict__ musig_in, const float* __restrict__ eps_prev,
    const float* __restrict__ b_mu, const float* __restrict__ b_sig, int pm1,
    // layer-1 head partials:
    const float* __restrict__ w_mu, const float* __restrict__ w_sig,
    float* __restrict__ musig_out)
{
    extern __shared__ __align__(128) char dsm[];
    unsigned* tAhi = (unsigned*)(dsm + DO_AH);
    unsigned* tBhi = (unsigned*)(dsm + DO_BH);
    float* sBias = (float*)(dsm + DO_BIAS);

    const int t    = threadIdx.x;
    const int lane = t & 31;
    const int wid  = t >> 5;
    const int m0w  = (wid & 1) * 64;
    const int u0w  = (wid >> 1) * 8;
    const int b0   = blockIdx.x * DBM;
    const int u0   = blockIdx.y * 32;

    const int lrow = t >> 1;
    const int lc0  = (t & 1) * 8;        // float col base
    const int lp0  = (t & 1) * 4;        // packed col base
    const int lgrow = u0 + (lrow & 31) + ((lrow >> 5) << 8);

    if (t < 128) {
        int grow = u0 + (t & 31) + ((t >> 5) << 8);
        sBias[t] = b_ih[grow] + b_hh[grow];
    }

    // ---- layer-0 prologue: materialize previous step's sample into hist ----
    if (musig_in != nullptr) {
        if (t < DBM) {
            int row = b0 + t;
            float mu = musig_in[row * 2]     + b_mu[0];
            float sg = musig_in[row * 2 + 1] + b_sig[0];
            float sp = (sg > 20.f) ? sg : log1pf(expf(sg));
            g_hist[row * 32 + MAXLAG + pm1] = mu + sp * eps_prev[row];
        }
        __syncthreads();
    }

    float acc[4][4][4];
#pragma unroll
    for (int mi = 0; mi < 4; mi++)
#pragma unroll
        for (int g = 0; g < 4; g++)
#pragma unroll
            for (int r = 0; r < 4; r++) acc[mi][g][r] = 0.f;

    const int qr = lane >> 2;
    const int qc = lane & 3;

    auto compute_chunk = [&](int buf) {
        const unsigned* AH = tAhi + buf * DTILEU;
        const unsigned* BH = tBhi + buf * DTILEU;
        unsigned ahi[4][4];
#pragma unroll
        for (int mi = 0; mi < 4; mi++) {
            int r = m0w + mi * 16 + qr;
            ahi[mi][0] = AH[r * DPK + qc];       ahi[mi][1] = AH[(r + 8) * DPK + qc];
            ahi[mi][2] = AH[r * DPK + qc + 4];   ahi[mi][3] = AH[(r + 8) * DPK + qc + 4];
        }
        unsigned bhi[4][2];
#pragma unroll
        for (int g = 0; g < 4; g++) {
            int br = g * 32 + u0w + qr;
            bhi[g][0] = BH[br * DPK + qc]; bhi[g][1] = BH[br * DPK + qc + 4];
        }
#pragma unroll
        for (int mi = 0; mi < 4; mi++)
#pragma unroll
            for (int g = 0; g < 4; g++)
                MMA_F16(acc[mi][g], ahi[mi], bhi[g]);
    };

    auto store_b8 = [&](int buf, const float* v) {
        unsigned hi[4];
#pragma unroll
        for (int j = 0; j < 4; j++) hi[j] = hpack2(v[2 * j], v[2 * j + 1]);
        *(uint4*)(tBhi + buf * DTILEU + lrow * DPK + lp0) = make_uint4(hi[0], hi[1], hi[2], hi[3]);
    };

    int tb = 0;

    // -------- lag chunk (K=7 zero-padded to 16): A packed at runtime --------
    if (xs != nullptr) {
        float va[8], vb[8];
#pragma unroll
        for (int cc = 0; cc < 8; cc++) {
            int k = lc0 + cc;
            va[cc] = (k < 7) ? xs[(b0 + lrow) * 32 - k] : 0.f;
            vb[cc] = (k < 7) ? w_ihs[lgrow * 7 + k] : 0.f;
        }
        unsigned hi[4];
#pragma unroll
        for (int j = 0; j < 4; j++) hi[j] = hpack2(va[2 * j], va[2 * j + 1]);
        *(uint4*)(tAhi + tb * DTILEU + lrow * DPK + lp0) = make_uint4(hi[0], hi[1], hi[2], hi[3]);
        store_b8(tb, vb);
        __syncthreads();
        compute_chunk(tb);
        tb ^= 1;
    }

    // -------- dense K=256 segments: A pure copy (fp16), B packed from fp32 --------
    auto gemm_segment = [&](const unsigned* __restrict__ act, const float* __restrict__ wgt) {
        for (int k0 = 0; k0 < HH; k0 += 16) {
            uint4 av = *(const uint4*)(act + (long long)(b0 + lrow) * HP + (k0 >> 1) + lp0);
            float wv[8];
            *(float4*)(wv)     = *(const float4*)(wgt + (long long)lgrow * HH + k0 + lc0);
            *(float4*)(wv + 4) = *(const float4*)(wgt + (long long)lgrow * HH + k0 + lc0 + 4);
            *(uint4*)(tAhi + tb * DTILEU + lrow * DPK + lp0) = av;
            store_b8(tb, wv);
            __syncthreads();
            compute_chunk(tb);
            tb ^= 1;
        }
    };

    if (xb != nullptr) gemm_segment(xb, w_ihb);
    gemm_segment(h_in, w_hh);

    // -------- epilogue: fused LSTM + packed h out + optional head partials --------
    float wmu[2] = {0.f, 0.f}, wsg[2] = {0.f, 0.f};
    if (w_mu != nullptr) {
#pragma unroll
        for (int j = 0; j < 2; j++) {
            int u = u0 + u0w + 2 * qc + j;
            wmu[j] = w_mu[u];
            wsg[j] = w_sig[u];
        }
    }
#pragma unroll
    for (int mi = 0; mi < 4; mi++) {
        int rbase = b0 + m0w + mi * 16 + qr;
#pragma unroll
        for (int half = 0; half < 2; half++) {
            int row = rbase + half * 8;
            float hn2[2];
#pragma unroll
            for (int j = 0; j < 2; j++) {
                int ucol = 2 * qc + j;
                int u = u0 + u0w + ucol;
                int ci = half * 2 + j;
                float gi_ = acc[mi][0][ci] + sBias[ 0 + u0w + ucol];
                float gf  = acc[mi][1][ci] + sBias[32 + u0w + ucol];
                float gg  = acc[mi][2][ci] + sBias[64 + u0w + ucol];
                float go  = acc[mi][3][ci] + sBias[96 + u0w + ucol];
                long long idx = (long long)row * HH + u;
                float c = c_in[idx];
                float cn = sigf(gf) * c + sigf(gi_) * tanhf(gg);
                float hn = sigf(go) * tanhf(cn);
                c_out[idx] = cn;
                hn2[j] = hn;
            }
            // packed h store: units (u0+u0w+2qc, +1) -> one half2
            h_out[(long long)row * HP + ((u0 + u0w) >> 1) + qc] = hpack2(hn2[0], hn2[1]);
            if (w_mu != nullptr) {
                float pm = hn2[0] * wmu[0] + hn2[1] * wmu[1];
                float ps = hn2[0] * wsg[0] + hn2[1] * wsg[1];
                pm += __shfl_xor_sync(0xffffffffu, pm, 1);
                ps += __shfl_xor_sync(0xffffffffu, ps, 1);
                pm += __shfl_xor_sync(0xffffffffu, pm, 2);
                ps += __shfl_xor_sync(0xffffffffu, ps, 2);
                if (qc == 0) {
                    atomicAdd(&musig_out[(long long)row * 2],     pm);
                    atomicAdd(&musig_out[(long long)row * 2 + 1], ps);
                }
            }
        }
    }
}

// ---------------- replicate encoder state x100 (packed fp16 h) + init history ----------------
__global__ void replicate_kernel() {
    int row = blockIdx.x;
    int u   = threadIdx.x;
    int b   = row / SREP;
    g_c0d[(long long)row * HH + u] = g_c0e[b * HH + u];
    g_c1d[(long long)row * HH + u] = g_c1e[b * HH + u];
    if (u < HP) {
        g_h0d[0][(long long)row * HP + u] = hpack2(g_h0e[0][b * HH + 2 * u], g_h0e[0][b * HH + 2 * u + 1]);
        g_h1d[0][(long long)row * HP + u] = hpack2(g_h1e[0][b * HH + 2 * u], g_h1e[0][b * HH + 2 * u + 1]);
    }
    if (u < MAXLAG) g_hist[row * 32 + u] = g_scaled[b * TT + WIN + u];
}

// ---------------- mean over samples (from musig) + denormalize ----------------
__global__ void reduce_kernel(float* __restrict__ out,
                              const float* __restrict__ eps,
                              const float* __restrict__ b_mu,
                              const float* __restrict__ b_sig) {
    int gid  = blockIdx.x * blockDim.x + threadIdx.x;
    int warp = gid >> 5;
    int lane = gid & 31;
    if (warp >= BATCH * PSTEPS) return;
    int b = warp / PSTEPS;
    int p = warp % PSTEPS;
    const float bmu = b_mu[0], bsg = b_sig[0];
    float s = 0.f;
    for (int ss = lane; ss < SREP; ss += 32) {
        long long row = (long long)b * SREP + ss;
        const float* ms = g_musig + ((long long)p * NDEC + row) * 2;
        float mu = ms[0] + bmu;
        float sg = ms[1] + bsg;
        float sp = (sg > 20.f) ? sg : log1pf(expf(sg));
        s += mu + sp * eps[(long long)p * NDEC + row];
    }
#pragma unroll
    for (int o = 16; o > 0; o >>= 1) s += __shfl_xor_sync(0xffffffffu, s, o);
    if (lane == 0)
        out[b * PSTEPS + p] = s * (1.0f / (float)SREP) * g_scale[b] + g_loc[b];
}

// ---------------- launch ----------------
extern "C" void kernel_launch(void* const* d_in, const int* in_sizes, int n_in,
                              void* d_out, int out_size) {
    const float* targets = (const float*)d_in[0];
    const float* w_ih0   = (const float*)d_in[1];
    const float* w_hh0   = (const float*)d_in[2];
    const float* b_ih0   = (const float*)d_in[3];
    const float* b_hh0   = (const float*)d_in[4];
    const float* w_ih1   = (const float*)d_in[5];
    const float* w_hh1   = (const float*)d_in[6];
    const float* b_ih1   = (const float*)d_in[7];
    const float* b_hh1   = (const float*)d_in[8];
    const float* w_mu    = (const float*)d_in[9];
    const float* b_mu    = (const float*)d_in[10];
    const float* w_sigma = (const float*)d_in[11];
    const float* b_sigma = (const float*)d_in[12];
    const float* eps     = (const float*)d_in[13];
    float* out = (float*)d_out;

    float *c0d, *c1d, *hist, *musig;
    unsigned *h0d, *h1d;
    cudaGetSymbolAddress((void**)&h0d, g_h0d);
    cudaGetSymbolAddress((void**)&h1d, g_h1d);
    cudaGetSymbolAddress((void**)&c0d, g_c0d);
    cudaGetSymbolAddress((void**)&c1d, g_c1d);
    cudaGetSymbolAddress((void**)&hist, g_hist);
    cudaGetSymbolAddress((void**)&musig, g_musig);

    cudaFuncSetAttribute(encoder_kernel,
                         cudaFuncAttributeMaxDynamicSharedMemorySize, ENC_SMEM_BYTES);
    cudaFuncSetAttribute(dec_cell_f16,
                         cudaFuncAttributeMaxDynamicSharedMemorySize, DEC_SMEM_BYTES);

    norm_kernel<<<BATCH, 256>>>(targets);
    zero_enc_kernel<<<(BATCH * HH + 255) / 256, 256>>>();
    zero_musig_kernel<<<1024, 256>>>();

    encoder_kernel<<<ENC_BLOCKS, 512, ENC_SMEM_BYTES>>>(
        w_ih0, w_hh0, b_ih0, b_hh0, w_ih1, w_hh1, b_ih1, b_hh1);

    replicate_kernel<<<NDEC, 256>>>();

    const long long NP = (long long)NDEC * HP;
    for (int p = 0; p < PSTEPS; p++) {
        int pa = p & 1, pb = pa ^ 1;
        const float* ms_in = (p > 0) ? (musig + (long long)(p - 1) * NDEC * 2) : nullptr;
        const float* ep    = (p > 0) ? (eps + (long long)(p - 1) * NDEC) : nullptr;
        // layer 0: sample prev step + lags + h0 @ w_hh0^T
        dec_cell_f16<<<dim3(NDEC / DBM, 8), 256, DEC_SMEM_BYTES>>>(
            hist + p + 6, w_ih0,
            nullptr, nullptr,
            h0d + pa * NP, w_hh0, b_ih0, b_hh0,
            c0d, h0d + pb * NP, c0d,
            ms_in, ep, b_mu, b_sigma, p - 1,
            nullptr, nullptr, nullptr);
        // layer 1: h0_new @ w_ih1^T + h1 @ w_hh1^T, fused head partials
        dec_cell_f16<<<dim3(NDEC / DBM, 8), 256, DEC_SMEM_BYTES>>>(
            nullptr, nullptr,
            h0d + pb * NP, w_ih1,
            h1d + pa * NP, w_hh1, b_ih1, b_hh1,
            c1d, h1d + pb * NP, c1d,
            nullptr, nullptr, nullptr, nullptr, 0,
            w_mu, w_sigma, musig + (long long)p * NDEC * 2);
    }

    reduce_kernel<<<(BATCH * PSTEPS * 32 + 255) / 256, 256>>>(out, eps, b_mu, b_sigma);
}

// round 17
// speedup vs baseline: 1.4212x; 1.0581x over previous
#include <cuda_runtime.h>
#include <cuda_bf16.h>
#include <cuda_fp16.h>
#include <cstdint>
#include <math.h>

#define HH      256
#define HP      128     // packed half2 per row
#define G4      1024
#define BATCH   256
#define WIN     512
#define TT      519     // W + MAXLAG
#define MAXLAG  7
#define SREP    100
#define NDEC    25600   // BATCH * SREP
#define PSTEPS  24
#define ESTEPS  512
#define ENC_BLOCKS 128

// ---- encoder v4 smem layout (4-byte units) ----
#define WPK    132
#define MATSZ  (2 * 64 * WPK)
#define OFF_CHH (3 * MATSZ)
#define OFF_CHL (OFF_CHH + 1536)
#define OFF_RED (OFF_CHL + 1536)
#define OFF_SXW (OFF_RED + 32 * 68)
#define OFF_SXA (OFF_SXW + 64 * 8)
#define ENC_SMEM_UNITS (OFF_SXA + 32 * 8)
#define ENC_SMEM_BYTES (ENC_SMEM_UNITS * 4)

// ---- decoder dynamic smem (bytes): fp16 1-pass, 2-buffer tiles + bias ----
#define DBM 128
#define DPK 12
#define DTILEU (DBM * DPK)
#define DO_AH  0
#define DO_BH  (2 * DTILEU * 4)
#define DO_BIAS (4 * DTILEU * 4)
#define DEC_SMEM_BYTES (DO_BIAS + 512)

// ---------------- scratch ----------------
__device__ __align__(128) float g_scaled[BATCH * TT];
__device__ float g_loc[BATCH];
__device__ float g_scale[BATCH];

__device__ __align__(128) float g_h0e[2][BATCH * HH];
__device__ __align__(128) float g_c0e[BATCH * HH];
__device__ __align__(128) float g_h1e[2][BATCH * HH];
__device__ __align__(128) float g_c1e[BATCH * HH];

// decoder h state: packed fp16 (half2 as unsigned), c fp32
__device__ __align__(128) unsigned g_h0d[2][NDEC * HP];
__device__ __align__(128) unsigned g_h1d[2][NDEC * HP];
__device__ __align__(128) float g_c0d[NDEC * HH];
__device__ __align__(128) float g_c1d[NDEC * HH];

// pre-packed fp16 decoder weights (half2 per 2 K): [mat][G4][128]; lag [G4][8]
__device__ __align__(128) unsigned g_w16[3][G4 * HP];
__device__ __align__(128) unsigned g_wlag16[G4 * 8];

__device__ __align__(128) float g_hist[NDEC * 32];
__device__ __align__(128) float g_musig[PSTEPS * NDEC * 2];

__device__ unsigned g_ectr = 0;

__device__ __forceinline__ float sigf(float x) { return 1.0f / (1.0f + expf(-x)); }

#define MMA_BF16(c, a, b) \
    asm volatile("mma.sync.aligned.m16n8k16.row.col.f32.bf16.bf16.f32 " \
                 "{%0,%1,%2,%3}, {%4,%5,%6,%7}, {%8,%9}, {%0,%1,%2,%3};\n" \
                 : "+f"((c)[0]), "+f"((c)[1]), "+f"((c)[2]), "+f"((c)[3]) \
                 : "r"((a)[0]), "r"((a)[1]), "r"((a)[2]), "r"((a)[3]), \
                   "r"((b)[0]), "r"((b)[1]))

#define MMA_F16(c, a, b) \
    asm volatile("mma.sync.aligned.m16n8k16.row.col.f32.f16.f16.f32 " \
                 "{%0,%1,%2,%3}, {%4,%5,%6,%7}, {%8,%9}, {%0,%1,%2,%3};\n" \
                 : "+f"((c)[0]), "+f"((c)[1]), "+f"((c)[2]), "+f"((c)[3]) \
                 : "r"((a)[0]), "r"((a)[1]), "r"((a)[2]), "r"((a)[3]), \
                   "r"((b)[0]), "r"((b)[1]))

__device__ __forceinline__ void bsplit2(float x, float y, unsigned& hi, unsigned& lo) {
    __nv_bfloat16 hx = __float2bfloat16(x);
    __nv_bfloat16 hy = __float2bfloat16(y);
    __nv_bfloat162 hp = __halves2bfloat162(hx, hy);
    __nv_bfloat162 lp = __halves2bfloat162(
        __float2bfloat16(x - __bfloat162float(hx)),
        __float2bfloat16(y - __bfloat162float(hy)));
    hi = *reinterpret_cast<unsigned*>(&hp);
    lo = *reinterpret_cast<unsigned*>(&lp);
}

__device__ __forceinline__ unsigned hpack2(float x, float y) {
    __half2 hp = __floats2half2_rn(x, y);
    return *reinterpret_cast<unsigned*>(&hp);
}

// ---------------- normalization ----------------
__global__ void norm_kernel(const float* __restrict__ tp) {
    int b = blockIdx.x;
    int tid = threadIdx.x;
    const float* row = tp + b * TT;

    double s = 0.0, q = 0.0;
    for (int j = tid; j < WIN; j += blockDim.x) {
        double v = (double)row[MAXLAG + j];
        s += v; q += v * v;
    }
    __shared__ double ss[256], sq[256];
    ss[tid] = s; sq[tid] = q;
    __syncthreads();
    for (int o = 128; o > 0; o >>= 1) {
        if (tid < o) { ss[tid] += ss[tid + o]; sq[tid] += sq[tid + o]; }
        __syncthreads();
    }
    __shared__ float smean, sscale;
    if (tid == 0) {
        double mean = ss[0] / (double)WIN;
        double var  = sq[0] / (double)WIN - mean * mean;
        if (var < 0.0) var = 0.0;
        float sd = (float)sqrt(var);
        float sc = (sd < 1e-10f) ? 1.0f : sd;
        smean = (float)mean; sscale = sc;
        g_loc[b] = (float)mean; g_scale[b] = sc;
    }
    __syncthreads();
    float m = smean, sc = sscale;
    for (int j = tid; j < TT; j += blockDim.x)
        g_scaled[b * TT + j] = (row[j] - m) / sc;
}

__global__ void zero_enc_kernel() {
    int i = blockIdx.x * blockDim.x + threadIdx.x;
    if (i < BATCH * HH) {
        g_h0e[0][i] = 0.f; g_c0e[i] = 0.f;
        g_h1e[0][i] = 0.f; g_c1e[i] = 0.f;
    }
    if (i == 0) g_ectr = 0;
}

__global__ void zero_musig_kernel() {
    int i = blockIdx.x * blockDim.x + threadIdx.x;
    int n = PSTEPS * NDEC * 2;
    for (; i < n; i += gridDim.x * blockDim.x) g_musig[i] = 0.f;
}

// ---------------- pack decoder weights to fp16 (once) ----------------
__global__ void pack_weights_f16(const float* __restrict__ w_hh0,
                                 const float* __restrict__ w_ih1,
                                 const float* __restrict__ w_hh1,
                                 const float* __restrict__ w_ih0) {
    int row = blockIdx.x;          // gate row 0..1023
    int kp  = threadIdx.x;         // 0..127
    g_w16[0][row * HP + kp] = hpack2(w_hh0[row * 256 + 2 * kp], w_hh0[row * 256 + 2 * kp + 1]);
    g_w16[1][row * HP + kp] = hpack2(w_ih1[row * 256 + 2 * kp], w_ih1[row * 256 + 2 * kp + 1]);
    g_w16[2][row * HP + kp] = hpack2(w_hh1[row * 256 + 2 * kp], w_hh1[row * 256 + 2 * kp + 1]);
    if (kp < 8) {
        float x = (2 * kp < 7)     ? w_ih0[row * 7 + 2 * kp]     : 0.f;
        float y = (2 * kp + 1 < 7) ? w_ih0[row * 7 + 2 * kp + 1] : 0.f;
        g_wlag16[row * 8 + kp] = hpack2(x, y);
    }
}

// ---------------- persistent encoder v4 (unchanged from R9/R13 wins) ----------------
__global__ void __launch_bounds__(512) encoder_kernel(
    const float* __restrict__ w_ih0, const float* __restrict__ w_hh0,
    const float* __restrict__ b_ih0, const float* __restrict__ b_hh0,
    const float* __restrict__ w_ih1, const float* __restrict__ w_hh1,
    const float* __restrict__ b_ih1, const float* __restrict__ b_hh1)
{
    extern __shared__ unsigned esu[];
    float* esf = reinterpret_cast<float*>(esu);
    unsigned* W0h  = esu;                 unsigned* W0l  = esu + 64 * WPK;
    unsigned* WI1h = esu + MATSZ;         unsigned* WI1l = esu + MATSZ + 64 * WPK;
    unsigned* WH1h = esu + 2 * MATSZ;     unsigned* WH1l = esu + 2 * MATSZ + 64 * WPK;
    unsigned* CHH  = esu + OFF_CHH;
    unsigned* CHL  = esu + OFF_CHL;
    float* RED = esf + OFF_RED;
    float* SXW = esf + OFF_SXW;
    float* SXA = esf + OFF_SXA;

    const int t    = threadIdx.x;
    const int lane = t & 31;
    const int w    = t >> 5;
    const int grp  = w >> 3;
    const int wl   = w & 7;
    const int m_w  = (wl & 1) * 16;
    const int n_w  = (wl >> 1) * 16;
    const int qr   = lane >> 2;
    const int qc   = lane & 3;
    const int b0   = (blockIdx.x & 7) * 32;
    const int u0   = (blockIdx.x >> 3) * 16;

    for (int i = t; i < 64 * 128; i += 512) {
        int r  = i >> 7;
        int kp = i & 127;
        int grow = u0 + (r & 15) + ((r >> 4) << 8);
        unsigned hi, lo;
        bsplit2(w_hh0[grow * 256 + 2 * kp], w_hh0[grow * 256 + 2 * kp + 1], hi, lo);
        W0h[r * WPK + kp] = hi;  W0l[r * WPK + kp] = lo;
        bsplit2(w_ih1[grow * 256 + 2 * kp], w_ih1[grow * 256 + 2 * kp + 1], hi, lo);
        WI1h[r * WPK + kp] = hi; WI1l[r * WPK + kp] = lo;
        bsplit2(w_hh1[grow * 256 + 2 * kp], w_hh1[grow * 256 + 2 * kp + 1], hi, lo);
        WH1h[r * WPK + kp] = hi; WH1l[r * WPK + kp] = lo;
    }
    if (t < 64) {
        int grow = u0 + (t & 15) + ((t >> 4) << 8);
#pragma unroll
        for (int k = 0; k < 7; k++) SXW[t * 8 + k] = w_ih0[grow * 7 + k];
    }

    const int eul = t & 15;
    const int er  = t >> 4;
    float bI0 = 0, bF0 = 0, bG0 = 0, bO0 = 0, bI1 = 0, bF1 = 0, bG1 = 0, bO1 = 0;
    if (t < 256) {
        int u = u0 + eul;
        bI0 = b_ih0[u]       + b_hh0[u];
        bF0 = b_ih0[u + 256] + b_hh0[u + 256];
        bG0 = b_ih0[u + 512] + b_hh0[u + 512];
        bO0 = b_ih0[u + 768] + b_hh0[u + 768];
        bI1 = b_ih1[u]       + b_hh1[u];
        bF1 = b_ih1[u + 256] + b_hh1[u + 256];
        bG1 = b_ih1[u + 512] + b_hh1[u + 512];
        bO1 = b_ih1[u + 768] + b_hh1[u + 768];
    }
    __syncthreads();

    const int gt   = t & 255;
    const int prow = gt >> 3;
    const int pc   = gt & 7;
    unsigned* CHHg = CHH + grp * 768;
    unsigned* CHLg = CHL + grp * 768;

    auto gemm_tc = [&](const float* act, const unsigned* Wh, const unsigned* Wl,
                       float (&acc)[2][4]) {
        const int kb  = grp * 128;
        const int kpb = grp * 64;
        {
            float2 p = __ldcg((const float2*)(act + (b0 + prow) * HH + kb + pc * 2));
            unsigned hi, lo; bsplit2(p.x, p.y, hi, lo);
            CHHg[prow * 12 + pc] = hi;
            CHLg[prow * 12 + pc] = lo;
        }
        __syncthreads();
        for (int ch = 0; ch < 8; ch++) {
            float2 nxt;
            const bool have = (ch + 1) < 8;
            if (have)
                nxt = __ldcg((const float2*)(act + (b0 + prow) * HH + kb + (ch + 1) * 16 + pc * 2));
            const unsigned* hbh = CHHg + (ch & 1) * 384;
            const unsigned* hbl = CHLg + (ch & 1) * 384;
            unsigned ahi[4], alo[4];
            ahi[0] = hbh[(m_w + qr) * 12 + qc];
            ahi[1] = hbh[(m_w + qr + 8) * 12 + qc];
            ahi[2] = hbh[(m_w + qr) * 12 + qc + 4];
            ahi[3] = hbh[(m_w + qr + 8) * 12 + qc + 4];
            alo[0] = hbl[(m_w + qr) * 12 + qc];
            alo[1] = hbl[(m_w + qr + 8) * 12 + qc];
            alo[2] = hbl[(m_w + qr) * 12 + qc + 4];
            alo[3] = hbl[(m_w + qr + 8) * 12 + qc + 4];
#pragma unroll
            for (int f = 0; f < 2; f++) {
                int wr  = (n_w + f * 8 + qr) * WPK + kpb + ch * 8;
                unsigned bhi[2] = {Wh[wr + qc], Wh[wr + qc + 4]};
                unsigned blo[2] = {Wl[wr + qc], Wl[wr + qc + 4]};
                MMA_BF16(acc[f], ahi, bhi);
                MMA_BF16(acc[f], ahi, blo);
                MMA_BF16(acc[f], alo, bhi);
            }
            if (have) {
                unsigned hi, lo; bsplit2(nxt.x, nxt.y, hi, lo);
                CHHg[((ch + 1) & 1) * 384 + prow * 12 + pc] = hi;
                CHLg[((ch + 1) & 1) * 384 + prow * 12 + pc] = lo;
            }
            __syncthreads();
        }
    };

    auto reduce_store = [&](float (&acc)[2][4]) {
        if (grp == 1) {
#pragma unroll
            for (int f = 0; f < 2; f++)
#pragma unroll
                for (int half = 0; half < 2; half++)
#pragma unroll
                    for (int j = 0; j < 2; j++)
                        RED[(m_w + qr + half * 8) * 68 + n_w + f * 8 + 2 * qc + j] =
                            acc[f][half * 2 + j];
        }
        __syncthreads();
        if (grp == 0) {
#pragma unroll
            for (int f = 0; f < 2; f++)
#pragma unroll
                for (int half = 0; half < 2; half++)
#pragma unroll
                    for (int j = 0; j < 2; j++)
                        RED[(m_w + qr + half * 8) * 68 + n_w + f * 8 + 2 * qc + j] +=
                            acc[f][half * 2 + j];
        }
        __syncthreads();
    };

    for (int step = 0; step < ESTEPS; step++) {
        const int pa = step & 1, pb = pa ^ 1;
        float* h0b = g_h0e[pb];
        float* h1b = g_h1e[pb];

        if (t < 32) {
            const float* xr = g_scaled + (b0 + t) * TT + step + 6;
#pragma unroll
            for (int k = 0; k < 7; k++) SXA[t * 8 + k] = xr[-k];
        }

        float acc[2][4];
#pragma unroll
        for (int f = 0; f < 2; f++)
#pragma unroll
            for (int r = 0; r < 4; r++) acc[f][r] = 0.f;

        gemm_tc(g_h0e[pa], W0h, W0l, acc);
        reduce_store(acc);

        if (t < 256) {
#pragma unroll
            for (int h2 = 0; h2 < 2; h2++) {
                int r = er + 16 * h2;
                float gi = RED[r * 68 + eul]      + bI0;
                float gf = RED[r * 68 + 16 + eul] + bF0;
                float gg = RED[r * 68 + 32 + eul] + bG0;
                float go = RED[r * 68 + 48 + eul] + bO0;
#pragma unroll
                for (int k = 0; k < 7; k++) {
                    float x = SXA[r * 8 + k];
                    gi = fmaf(x, SXW[eul * 8 + k], gi);
                    gf = fmaf(x, SXW[(16 + eul) * 8 + k], gf);
                    gg = fmaf(x, SXW[(32 + eul) * 8 + k], gg);
                    go = fmaf(x, SXW[(48 + eul) * 8 + k], go);
                }
                int idx = (b0 + r) * HH + (u0 + eul);
                float c = g_c0e[idx];
                float cn = sigf(gf) * c + sigf(gi) * tanhf(gg);
                g_c0e[idx] = cn;
                h0b[idx] = sigf(go) * tanhf(cn);
            }
        }
        __syncthreads();
        if (t == 0) { __threadfence(); atomicAdd(&g_ectr, 1u); }

#pragma unroll
        for (int f = 0; f < 2; f++)
#pragma unroll
            for (int r = 0; r < 4; r++) acc[f][r] = 0.f;

        if (t == 0) {
            unsigned tgt = 256u * (unsigned)step;
            while (*(volatile unsigned*)&g_ectr < tgt) { }
        }
        __syncthreads();
        gemm_tc(g_h1e[pa], WH1h, WH1l, acc);

        if (t == 0) {
            unsigned tgt = 256u * (unsigned)step + 128u;
            while (*(volatile unsigned*)&g_ectr < tgt) { }
        }
        __syncthreads();
        gemm_tc(h0b, WI1h, WI1l, acc);

        reduce_store(acc);

        if (t < 256) {
#pragma unroll
            for (int h2 = 0; h2 < 2; h2++) {
                int r = er + 16 * h2;
                float gi = RED[r * 68 + eul]      + bI1;
                float gf = RED[r * 68 + 16 + eul] + bF1;
                float gg = RED[r * 68 + 32 + eul] + bG1;
                float go = RED[r * 68 + 48 + eul] + bO1;
                int idx = (b0 + r) * HH + (u0 + eul);
                float c = g_c1e[idx];
                float cn = sigf(gf) * c + sigf(gi) * tanhf(gg);
                g_c1e[idx] = cn;
                h1b[idx] = sigf(go) * tanhf(cn);
            }
        }
        __syncthreads();
        if (t == 0) { __threadfence(); atomicAdd(&g_ectr, 1u); }
    }
}

// ---------------- decoder cell v10: fp16 1-pass, all operands pure copy ----------------
__global__ void __launch_bounds__(256) dec_cell_f16(
    const float* __restrict__ xs,          // lag base (g_hist + p + 6) or null
    const unsigned* __restrict__ wlag,     // packed lag weights or null
    const unsigned* __restrict__ xb,       // big x packed fp16 (N,128) or null
    const unsigned* __restrict__ wb16,     // packed weights for xb segment
    const unsigned* __restrict__ h_in,     // packed fp16 (N,128)
    const unsigned* __restrict__ wh16,     // packed weights for h segment
    const float* __restrict__ b_ih, const float* __restrict__ b_hh,
    const float* __restrict__ c_in,
    unsigned* __restrict__ h_out, float* __restrict__ c_out,
    // layer-0 sampling prologue (p>0):
    const float* __restrict__ musig_in, const float* __restrict__ eps_prev,
    const float* __restrict__ b_mu, const float* __restrict__ b_sig, int pm1,
    // layer-1 head partials:
    const float* __restrict__ w_mu, const float* __restrict__ w_sig,
    float* __restrict__ musig_out)
{
    extern __shared__ __align__(128) char dsm[];
    unsigned* tAhi = (unsigned*)(dsm + DO_AH);
    unsigned* tBhi = (unsigned*)(dsm + DO_BH);
    float* sBias = (float*)(dsm + DO_BIAS);

    const int t    = threadIdx.x;
    const int lane = t & 31;
    const int wid  = t >> 5;
    const int m0w  = (wid & 1) * 64;
    const int u0w  = (wid >> 1) * 8;
    const int b0   = blockIdx.x * DBM;
    const int u0   = blockIdx.y * 32;

    const int lrow = t >> 1;
    const int lc0  = (t & 1) * 8;        // float col base
    const int lp0  = (t & 1) * 4;        // packed col base
    const int lgrow = u0 + (lrow & 31) + ((lrow >> 5) << 8);

    if (t < 128) {
        int grow = u0 + (t & 31) + ((t >> 5) << 8);
        sBias[t] = b_ih[grow] + b_hh[grow];
    }

    // ---- layer-0 prologue: materialize previous step's sample into hist ----
    if (musig_in != nullptr) {
        if (t < DBM) {
            int row = b0 + t;
            float mu = musig_in[row * 2]     + b_mu[0];
            float sg = musig_in[row * 2 + 1] + b_sig[0];
            float sp = (sg > 20.f) ? sg : log1pf(expf(sg));
            g_hist[row * 32 + MAXLAG + pm1] = mu + sp * eps_prev[row];
        }
        __syncthreads();
    }

    float acc[4][4][4];
#pragma unroll
    for (int mi = 0; mi < 4; mi++)
#pragma unroll
        for (int g = 0; g < 4; g++)
#pragma unroll
            for (int r = 0; r < 4; r++) acc[mi][g][r] = 0.f;

    const int qr = lane >> 2;
    const int qc = lane & 3;

    auto compute_chunk = [&](int buf) {
        const unsigned* AH = tAhi + buf * DTILEU;
        const unsigned* BH = tBhi + buf * DTILEU;
        unsigned ahi[4][4];
#pragma unroll
        for (int mi = 0; mi < 4; mi++) {
            int r = m0w + mi * 16 + qr;
            ahi[mi][0] = AH[r * DPK + qc];       ahi[mi][1] = AH[(r + 8) * DPK + qc];
            ahi[mi][2] = AH[r * DPK + qc + 4];   ahi[mi][3] = AH[(r + 8) * DPK + qc + 4];
        }
        unsigned bhi[4][2];
#pragma unroll
        for (int g = 0; g < 4; g++) {
            int br = g * 32 + u0w + qr;
            bhi[g][0] = BH[br * DPK + qc]; bhi[g][1] = BH[br * DPK + qc + 4];
        }
#pragma unroll
        for (int mi = 0; mi < 4; mi++)
#pragma unroll
            for (int g = 0; g < 4; g++)
                MMA_F16(acc[mi][g], ahi[mi], bhi[g]);
    };

    int tb = 0;

    // -------- lag chunk (K=7 zero-padded to 16): A packed at runtime, B copy --------
    if (xs != nullptr) {
        float va[8];
#pragma unroll
        for (int cc = 0; cc < 8; cc++) {
            int k = lc0 + cc;
            va[cc] = (k < 7) ? xs[(b0 + lrow) * 32 - k] : 0.f;
        }
        unsigned hi[4];
#pragma unroll
        for (int j = 0; j < 4; j++) hi[j] = hpack2(va[2 * j], va[2 * j + 1]);
        *(uint4*)(tAhi + tb * DTILEU + lrow * DPK + lp0) = make_uint4(hi[0], hi[1], hi[2], hi[3]);
        *(uint4*)(tBhi + tb * DTILEU + lrow * DPK + lp0) =
            *(const uint4*)(wlag + lgrow * 8 + lp0);
        __syncthreads();
        compute_chunk(tb);
        tb ^= 1;
    }

    // -------- dense K=256 segments: both operands pure uint4 copy --------
    auto gemm_segment = [&](const unsigned* __restrict__ act, const unsigned* __restrict__ w16) {
        for (int kp = 0; kp < HP; kp += 8) {
            uint4 av = *(const uint4*)(act + (long long)(b0 + lrow) * HP + kp + lp0);
            uint4 bv = *(const uint4*)(w16 + (long long)lgrow * HP + kp + lp0);
            *(uint4*)(tAhi + tb * DTILEU + lrow * DPK + lp0) = av;
            *(uint4*)(tBhi + tb * DTILEU + lrow * DPK + lp0) = bv;
            __syncthreads();
            compute_chunk(tb);
            tb ^= 1;
        }
    };

    if (xb != nullptr) gemm_segment(xb, wb16);
    gemm_segment(h_in, wh16);

    // -------- epilogue: fused LSTM + packed h out + optional head partials --------
    float wmu[2] = {0.f, 0.f}, wsg[2] = {0.f, 0.f};
    if (w_mu != nullptr) {
#pragma unroll
        for (int j = 0; j < 2; j++) {
            int u = u0 + u0w + 2 * qc + j;
            wmu[j] = w_mu[u];
            wsg[j] = w_sig[u];
        }
    }
#pragma unroll
    for (int mi = 0; mi < 4; mi++) {
        int rbase = b0 + m0w + mi * 16 + qr;
#pragma unroll
        for (int half = 0; half < 2; half++) {
            int row = rbase + half * 8;
            float hn2[2];
#pragma unroll
            for (int j = 0; j < 2; j++) {
                int ucol = 2 * qc + j;
                int u = u0 + u0w + ucol;
                int ci = half * 2 + j;
                float gi_ = acc[mi][0][ci] + sBias[ 0 + u0w + ucol];
                float gf  = acc[mi][1][ci] + sBias[32 + u0w + ucol];
                float gg  = acc[mi][2][ci] + sBias[64 + u0w + ucol];
                float go  = acc[mi][3][ci] + sBias[96 + u0w + ucol];
                long long idx = (long long)row * HH + u;
                float c = c_in[idx];
                float cn = sigf(gf) * c + sigf(gi_) * tanhf(gg);
                float hn = sigf(go) * tanhf(cn);
                c_out[idx] = cn;
                hn2[j] = hn;
            }
            h_out[(long long)row * HP + ((u0 + u0w) >> 1) + qc] = hpack2(hn2[0], hn2[1]);
            if (w_mu != nullptr) {
                float pm = hn2[0] * wmu[0] + hn2[1] * wmu[1];
                float ps = hn2[0] * wsg[0] + hn2[1] * wsg[1];
                pm += __shfl_xor_sync(0xffffffffu, pm, 1);
                ps += __shfl_xor_sync(0xffffffffu, ps, 1);
                pm += __shfl_xor_sync(0xffffffffu, pm, 2);
                ps += __shfl_xor_sync(0xffffffffu, ps, 2);
                if (qc == 0) {
                    atomicAdd(&musig_out[(long long)row * 2],     pm);
                    atomicAdd(&musig_out[(long long)row * 2 + 1], ps);
                }
            }
        }
    }
}

// ---------------- replicate encoder state x100 (packed fp16 h) + init history ----------------
__global__ void replicate_kernel() {
    int row = blockIdx.x;
    int u   = threadIdx.x;
    int b   = row / SREP;
    g_c0d[(long long)row * HH + u] = g_c0e[b * HH + u];
    g_c1d[(long long)row * HH + u] = g_c1e[b * HH + u];
    if (u < HP) {
        g_h0d[0][(long long)row * HP + u] = hpack2(g_h0e[0][b * HH + 2 * u], g_h0e[0][b * HH + 2 * u + 1]);
        g_h1d[0][(long long)row * HP + u] = hpack2(g_h1e[0][b * HH + 2 * u], g_h1e[0][b * HH + 2 * u + 1]);
    }
    if (u < MAXLAG) g_hist[row * 32 + u] = g_scaled[b * TT + WIN + u];
}

// ---------------- mean over samples (from musig) + denormalize ----------------
__global__ void reduce_kernel(float* __restrict__ out,
                              const float* __restrict__ eps,
                              const float* __restrict__ b_mu,
                              const float* __restrict__ b_sig) {
    int gid  = blockIdx.x * blockDim.x + threadIdx.x;
    int warp = gid >> 5;
    int lane = gid & 31;
    if (warp >= BATCH * PSTEPS) return;
    int b = warp / PSTEPS;
    int p = warp % PSTEPS;
    const float bmu = b_mu[0], bsg = b_sig[0];
    float s = 0.f;
    for (int ss = lane; ss < SREP; ss += 32) {
        long long row = (long long)b * SREP + ss;
        const float* ms = g_musig + ((long long)p * NDEC + row) * 2;
        float mu = ms[0] + bmu;
        float sg = ms[1] + bsg;
        float sp = (sg > 20.f) ? sg : log1pf(expf(sg));
        s += mu + sp * eps[(long long)p * NDEC + row];
    }
#pragma unroll
    for (int o = 16; o > 0; o >>= 1) s += __shfl_xor_sync(0xffffffffu, s, o);
    if (lane == 0)
        out[b * PSTEPS + p] = s * (1.0f / (float)SREP) * g_scale[b] + g_loc[b];
}

// ---------------- launch ----------------
extern "C" void kernel_launch(void* const* d_in, const int* in_sizes, int n_in,
                              void* d_out, int out_size) {
    const float* targets = (const float*)d_in[0];
    const float* w_ih0   = (const float*)d_in[1];
    const float* w_hh0   = (const float*)d_in[2];
    const float* b_ih0   = (const float*)d_in[3];
    const float* b_hh0   = (const float*)d_in[4];
    const float* w_ih1   = (const float*)d_in[5];
    const float* w_hh1   = (const float*)d_in[6];
    const float* b_ih1   = (const float*)d_in[7];
    const float* b_hh1   = (const float*)d_in[8];
    const float* w_mu    = (const float*)d_in[9];
    const float* b_mu    = (const float*)d_in[10];
    const float* w_sigma = (const float*)d_in[11];
    const float* b_sigma = (const float*)d_in[12];
    const float* eps     = (const float*)d_in[13];
    float* out = (float*)d_out;

    float *c0d, *c1d, *hist, *musig;
    unsigned *h0d, *h1d, *w16, *wlag16;
    cudaGetSymbolAddress((void**)&h0d, g_h0d);
    cudaGetSymbolAddress((void**)&h1d, g_h1d);
    cudaGetSymbolAddress((void**)&c0d, g_c0d);
    cudaGetSymbolAddress((void**)&c1d, g_c1d);
    cudaGetSymbolAddress((void**)&hist, g_hist);
    cudaGetSymbolAddress((void**)&musig, g_musig);
    cudaGetSymbolAddress((void**)&w16, g_w16);
    cudaGetSymbolAddress((void**)&wlag16, g_wlag16);

    cudaFuncSetAttribute(encoder_kernel,
                         cudaFuncAttributeMaxDynamicSharedMemorySize, ENC_SMEM_BYTES);
    cudaFuncSetAttribute(dec_cell_f16,
                         cudaFuncAttributeMaxDynamicSharedMemorySize, DEC_SMEM_BYTES);

    norm_kernel<<<BATCH, 256>>>(targets);
    zero_enc_kernel<<<(BATCH * HH + 255) / 256, 256>>>();
    zero_musig_kernel<<<1024, 256>>>();
    pack_weights_f16<<<G4, 128>>>(w_hh0, w_ih1, w_hh1, w_ih0);

    encoder_kernel<<<ENC_BLOCKS, 512, ENC_SMEM_BYTES>>>(
        w_ih0, w_hh0, b_ih0, b_hh0, w_ih1, w_hh1, b_ih1, b_hh1);

    replicate_kernel<<<NDEC, 256>>>();

    const long long NP = (long long)NDEC * HP;
    for (int p = 0; p < PSTEPS; p++) {
        int pa = p & 1, pb = pa ^ 1;
        const float* ms_in = (p > 0) ? (musig + (long long)(p - 1) * NDEC * 2) : nullptr;
        const float* ep    = (p > 0) ? (eps + (long long)(p - 1) * NDEC) : nullptr;
        // layer 0: sample prev step + lags + h0 @ w_hh0^T (mat 0)
        dec_cell_f16<<<dim3(NDEC / DBM, 8), 256, DEC_SMEM_BYTES>>>(
            hist + p + 6, wlag16,
            nullptr, nullptr,
            h0d + pa * NP, w16 + 0 * (G4 * HP),
            b_ih0, b_hh0, c0d,
            h0d + pb * NP, c0d,
            ms_in, ep, b_mu, b_sigma, p - 1,
            nullptr, nullptr, nullptr);
        // layer 1: h0_new @ w_ih1^T (mat 1) + h1 @ w_hh1^T (mat 2), fused head
        dec_cell_f16<<<dim3(NDEC / DBM, 8), 256, DEC_SMEM_BYTES>>>(
            nullptr, nullptr,
            h0d + pb * NP, w16 + 1 * (G4 * HP),
            h1d + pa * NP, w16 + 2 * (G4 * HP),
            b_ih1, b_hh1, c1d,
            h1d + pb * NP, c1d,
            nullptr, nullptr, nullptr, nullptr, 0,
            w_mu, w_sigma, musig + (long long)p * NDEC * 2);
    }

    reduce_kernel<<<(BATCH * PSTEPS * 32 + 255) / 256, 256>>>(out, eps, b_mu, b_sigma);
}